// round 12
// baseline (speedup 1.0000x reference)
#include <cuda_runtime.h>
#include <cuda_bf16.h>
#include <math.h>

#define EPS 1e-5f
#define BB_ 4
#define CIN 512
#define CI 64
#define HW 4096
#define NSPLIT 4

// ---------------- scratch (device globals, no allocation) ----------------
__device__ float g_fp[BB_*CI*HW];
__device__ float g_fcb[BB_*CI*HW];
__device__ float g_gram[BB_*CI*CI];
__device__ float g_attn[BB_*CI*CI];
__device__ float g_opart[NSPLIT*BB_*CI*HW];  // partial attention O, NSPLIT k-splits
__device__ float g_lsum[NSPLIT*BB_*HW];      // partial softmax denominators
// bf16 tensors for mma attention, all pixel-major [b][px][c]
__device__ __nv_bfloat16 g_fbt[BB_*HW*CI];   // Q
__device__ __nv_bfloat16 g_fct[BB_*HW*CI];   // K
__device__ __nv_bfloat16 g_fdt[BB_*HW*CI];   // V

// ================= PTX helpers (baseline ISA only, sm_80+) =================
static __device__ __forceinline__ unsigned smem_u32(const void* p){
    unsigned a; asm("{ .reg .u64 t; cvta.to.shared.u64 t, %1; cvt.u32.u64 %0, t; }":"=r"(a):"l"(p)); return a;
}
static __device__ __forceinline__ unsigned pack_bf16x2(float lo, float hi){
    unsigned r; asm("cvt.rn.bf16x2.f32 %0, %1, %2;" : "=r"(r) : "f"(hi), "f"(lo)); return r;
}
static __device__ __forceinline__ void ldsm4(unsigned* r, unsigned addr){
    asm volatile("ldmatrix.sync.aligned.m8n8.x4.shared.b16 {%0,%1,%2,%3}, [%4];"
        : "=r"(r[0]),"=r"(r[1]),"=r"(r[2]),"=r"(r[3]) : "r"(addr));
}
static __device__ __forceinline__ void ldsm4t(unsigned* r, unsigned addr){
    asm volatile("ldmatrix.sync.aligned.m8n8.x4.trans.shared.b16 {%0,%1,%2,%3}, [%4];"
        : "=r"(r[0]),"=r"(r[1]),"=r"(r[2]),"=r"(r[3]) : "r"(addr));
}
static __device__ __forceinline__ void mma16816(float* d, const unsigned* a, unsigned b0, unsigned b1){
    asm volatile("mma.sync.aligned.m16n8k16.row.col.f32.bf16.bf16.f32 "
        "{%0,%1,%2,%3}, {%4,%5,%6,%7}, {%8,%9}, {%0,%1,%2,%3};"
        : "+f"(d[0]),"+f"(d[1]),"+f"(d[2]),"+f"(d[3])
        : "r"(a[0]),"r"(a[1]),"r"(a[2]),"r"(a[3]), "r"(b0),"r"(b1));
}
static __device__ __forceinline__ void mma1688t(float* d, const unsigned* a, unsigned b0, unsigned b1){
    asm volatile("mma.sync.aligned.m16n8k8.row.col.f32.tf32.tf32.f32 "
        "{%0,%1,%2,%3}, {%4,%5,%6,%7}, {%8,%9}, {%0,%1,%2,%3};"
        : "+f"(d[0]),"+f"(d[1]),"+f"(d[2]),"+f"(d[3])
        : "r"(a[0]),"r"(a[1]),"r"(a[2]),"r"(a[3]), "r"(b0),"r"(b1));
}
static __device__ __forceinline__ unsigned f2t(float v){
    unsigned r; asm("cvt.rna.tf32.f32 %0, %1;" : "=r"(r) : "f"(v)); return r;
}
static __device__ __forceinline__ void split_tf32(float v, unsigned& hi, unsigned& lo){
    hi = f2t(v);
    lo = f2t(v - __uint_as_float(hi));
}
#define CPA(dst, src) asm volatile("cp.async.ca.shared.global [%0], [%1], 16;" :: "r"(dst), "l"(src))
#define CP_COMMIT()   asm volatile("cp.async.commit_group;" ::: "memory")
#define CP_WAIT(n)    asm volatile("cp.async.wait_group %0;" :: "n"(n) : "memory")

// ---------------- zero gram ----------------
__global__ void kZero() {
    int i = blockIdx.x*blockDim.x + threadIdx.x;
    if (i < BB_*CI*CI) g_gram[i] = 0.f;
}

// ---------------- K1 (tf32x3 mma): x(512) -> fp(64), fcb(64) with BN fold ----------------
__global__ __launch_bounds__(256) void kA(
    const float* __restrict__ x,
    const float* __restrict__ wp1, const float* __restrict__ gp1, const float* __restrict__ bp1,
    const float* __restrict__ mp1, const float* __restrict__ vp1,
    const float* __restrict__ wc1, const float* __restrict__ gc1, const float* __restrict__ bc1,
    const float* __restrict__ mc1, const float* __restrict__ vc1)
{
    extern __shared__ char smraw[];
    float* sWf[2] = {(float*)smraw, (float*)(smraw+18432)};
    float* sXf[2] = {(float*)(smraw+36864), (float*)(smraw+36864+16896)};
    unsigned ub = smem_u32(smraw);
    unsigned uW[2] = {ub, ub+18432};
    unsigned uX[2] = {ub+36864, ub+36864+16896};

    int b = blockIdx.y, p0 = blockIdx.x*128;
    int tid=threadIdx.x, lane=tid&31, w=tid>>5;
    int wm=w>>2, wn=w&3;
    const float* xb = x + (size_t)b*CIN*HW + p0;

    const float* wsrc[4]; unsigned wdst[4];
    const float* xsrc[4]; unsigned xdst[4]; int xk[4];
#pragma unroll
    for (int s=0;s<4;s++){
        int idx = tid + s*256;
        int o = idx>>3, kq = (idx&7)*4;
        wsrc[s] = (o<64 ? wp1 + (size_t)o*CIN : wc1 + (size_t)(o-64)*CIN) + kq;
        wdst[s] = (unsigned)((o*36 + kq)*4);
        int k = idx>>5, pq = (idx&31)*4;
        xk[s] = k;
        xsrc[s] = xb + pq;
        xdst[s] = (unsigned)((k*132 + pq)*4);
    }
#pragma unroll
    for (int s=0;s<4;s++){
        CPA(uW[0]+wdst[s], wsrc[s]);
        CPA(uX[0]+xdst[s], xsrc[s] + (size_t)xk[s]*HW);
    }
    CP_COMMIT();

    float acc[4][4][4];
#pragma unroll
    for (int mt=0;mt<4;mt++)
#pragma unroll
        for (int nt=0;nt<4;nt++){ acc[mt][nt][0]=0.f; acc[mt][nt][1]=0.f; acc[mt][nt][2]=0.f; acc[mt][nt][3]=0.f; }

    int orow = wm*64 + (lane>>2);
    int pxr  = wn*32 + (lane>>2);

    for (int c=0;c<16;c++){
        if (c<15){
            int k0 = (c+1)*32; int nb=(c+1)&1;
#pragma unroll
            for (int s=0;s<4;s++){
                CPA(uW[nb]+wdst[s], wsrc[s]+k0);
                CPA(uX[nb]+xdst[s], xsrc[s] + (size_t)(k0+xk[s])*HW);
            }
            CP_COMMIT(); CP_WAIT(1);
        } else { CP_WAIT(0); }
        __syncthreads();
        const float* Wb = sWf[c&1]; const float* Xb = sXf[c&1];
#pragma unroll
        for (int ks=0;ks<4;ks++){
            int kk = ks*8 + (lane&3);
            unsigned Ah[4][4], Al[4][4];
#pragma unroll
            for (int mt=0;mt<4;mt++){
                int ro = (orow + mt*16)*36;
                split_tf32(Wb[ro+kk],        Ah[mt][0], Al[mt][0]);
                split_tf32(Wb[ro+8*36+kk],   Ah[mt][1], Al[mt][1]);
                split_tf32(Wb[ro+kk+4],      Ah[mt][2], Al[mt][2]);
                split_tf32(Wb[ro+8*36+kk+4], Ah[mt][3], Al[mt][3]);
            }
            unsigned Bh[4][2], Bl[4][2];
#pragma unroll
            for (int nt=0;nt<4;nt++){
                split_tf32(Xb[kk*132 + pxr + nt*8],     Bh[nt][0], Bl[nt][0]);
                split_tf32(Xb[(kk+4)*132 + pxr + nt*8], Bh[nt][1], Bl[nt][1]);
            }
#pragma unroll
            for (int mt=0;mt<4;mt++)
#pragma unroll
                for (int nt=0;nt<4;nt++){
                    mma1688t(acc[mt][nt], Al[mt], Bh[nt][0], Bh[nt][1]);
                    mma1688t(acc[mt][nt], Ah[mt], Bl[nt][0], Bl[nt][1]);
                    mma1688t(acc[mt][nt], Ah[mt], Bh[nt][0], Bh[nt][1]);
                }
        }
        __syncthreads();
    }
#pragma unroll
    for (int mt=0;mt<4;mt++){
#pragma unroll
        for (int sel=0;sel<2;sel++){
            int oc = wm*64 + mt*16 + (lane>>2) + sel*8;
            float inv, bias; float* dst;
            if (oc<64){ inv=gp1[oc]*rsqrtf(vp1[oc]+EPS); bias=bp1[oc]-mp1[oc]*inv;
                        dst=g_fp+(size_t)(b*CI+oc)*HW; }
            else      { int o2=oc-64; inv=gc1[o2]*rsqrtf(vc1[o2]+EPS); bias=bc1[o2]-mc1[o2]*inv;
                        dst=g_fcb+(size_t)(b*CI+o2)*HW; }
#pragma unroll
            for (int nt=0;nt<4;nt++){
                float2 v;
                v.x = acc[mt][nt][sel*2+0]*inv+bias;
                v.y = acc[mt][nt][sel*2+1]*inv+bias;
                *(float2*)&dst[p0 + wn*32 + nt*8 + (lane&3)*2] = v;
            }
        }
    }
}

// ---------------- K2: fp(64) -> Q/K/V pixel-major bf16, all 3 in one CTA ----------------
__global__ __launch_bounds__(256) void kB(
    const float* __restrict__ wb,  const float* __restrict__ bb,
    const float* __restrict__ wc2, const float* __restrict__ bc2,
    const float* __restrict__ wd,  const float* __restrict__ bd)
{
    extern __shared__ float sm[];
    float* sW3 = sm;                         // [3][64][68]
    float (*sF)[132] = (float(*)[132])(sm + 3*64*68);  // [k][p]
    int p0 = blockIdx.x*128, b = blockIdx.y;
    int tid=threadIdx.x, ty=tid>>4, tx=tid&15;

    const float* Ws[3] = {wb, wc2, wd};
#pragma unroll
    for (int sel=0;sel<3;sel++){
        float* sW = sW3 + sel*64*68;
#pragma unroll
        for (int s=0;s<4;s++){
            int idx = tid + s*256;
            int j = idx>>4, cc = (idx&15)*4;
            float4 v = *(const float4*)(Ws[sel] + j*64 + cc);
            sW[(cc+0)*68+j]=v.x; sW[(cc+1)*68+j]=v.y; sW[(cc+2)*68+j]=v.z; sW[(cc+3)*68+j]=v.w;
        }
    }
    const float* fpb = g_fp + (size_t)b*CI*HW + p0;
#pragma unroll
    for (int s=0;s<8;s++){
        int idx = tid + s*256;
        int k = idx>>5, pc = (idx&31)*4;
        *(float4*)&sF[k][pc] = *(const float4*)(fpb + (size_t)k*HW + pc);
    }
    __syncthreads();
    const float* biasArr[3] = {bb, bc2, bd};
    __nv_bfloat16* dsts[3] = {g_fbt, g_fct, g_fdt};
#pragma unroll
    for (int sel=0;sel<3;sel++){
        const float* sW = sW3 + sel*64*68;
        const float* bias = biasArr[sel];
        float acc[4][8];
#pragma unroll
        for (int i=0;i<4;i++)
#pragma unroll
            for (int j=0;j<8;j++) acc[i][j]=0.f;
        for (int k=0;k<64;k++){
            float a[4], bv[8];
#pragma unroll
            for (int i=0;i<4;i++) a[i]=sW[k*68 + ty*4+i];
#pragma unroll
            for (int j=0;j<8;j++) bv[j]=sF[k][tx*8+j];
#pragma unroll
            for (int i=0;i<4;i++)
#pragma unroll
                for (int j=0;j<8;j++)
                    acc[i][j] = fmaf(a[i], bv[j], acc[i][j]);
        }
        __nv_bfloat16* dstT = dsts[sel] + ((size_t)b*HW + p0)*CI;
        float bi0=bias[ty*4+0], bi1=bias[ty*4+1], bi2=bias[ty*4+2], bi3=bias[ty*4+3];
#pragma unroll
        for (int j=0;j<8;j++){
            uint2 v;
            v.x = pack_bf16x2(acc[0][j]+bi0, acc[1][j]+bi1);
            v.y = pack_bf16x2(acc[2][j]+bi2, acc[3][j]+bi3);
            *(uint2*)((char*)dstT + ((size_t)(tx*8+j)*CI + ty*4)*2) = v;
        }
    }
}

// ---------------- K3: mma.sync flash attention, k-split x4, cp.async double-buffered ----------------
// grid (32 q-blocks, 4 k-splits, 4 batch), 256 thr (8 warps x 16 q-rows)
#define QSTR 144   // bytes per smem row (72 bf16)
__global__ __launch_bounds__(256) void kCm()
{
    extern __shared__ char smem[];
    const int SKb0=0, SKb1=18432, SVb0=36864, SVb1=55296;   // total 73728
    float* sOut = (float*)smem;           // reused after mainloop: [64][132]
    unsigned sb = smem_u32(smem);
    int tid=threadIdx.x, lane=tid&31, w=tid>>5;
    int b=blockIdx.z, ks=blockIdx.y, q0=blockIdx.x*128;
    int g = lane>>2, tg = lane&3;
    const int NT = 32/NSPLIT;             // 8 tiles per split
    const int T0 = ks*NT;

    const char* Qg = (const char*)(g_fbt + ((size_t)b*HW + q0)*CI);
    const char* Kg = (const char*)(g_fct + (size_t)b*HW*CI);
    const char* Vg = (const char*)(g_fdt + (size_t)b*HW*CI);

    int pxl[4], chl[4];
#pragma unroll
    for (int s=0;s<4;s++){ int idx = tid + s*256; pxl[s]=idx>>3; chl[s]=(idx&7)*8; }

    // prologue: Q staged into SKb1, first K/V tile into SKb0/SVb0
#pragma unroll
    for (int s=0;s<4;s++){
        unsigned so = (unsigned)(pxl[s]*QSTR + chl[s]*2);
        size_t  go = ((size_t)pxl[s]*CI + chl[s])*2;
        size_t  gk = (((size_t)T0*128 + pxl[s])*CI + chl[s])*2;
        CPA(sb+SKb1+so, Qg + go);
        CPA(sb+SKb0+so, Kg + gk);
        CPA(sb+SVb0+so, Vg + gk);
    }
    CP_COMMIT(); CP_WAIT(0);
    __syncthreads();

    // extract Q fragments from SKb1, then release the buffer
    unsigned aQ[4][4];
    {
        unsigned rb = sb + SKb1 + (unsigned)((16*w + (lane&15))*QSTR) + (unsigned)((lane>>4)*16);
#pragma unroll
        for (int kq=0; kq<4; kq++) ldsm4(aQ[kq], rb + kq*32);
    }
    __syncthreads();

    float oacc[8][4];
#pragma unroll
    for (int i=0;i<8;i++){ oacc[i][0]=0.f; oacc[i][1]=0.f; oacc[i][2]=0.f; oacc[i][3]=0.f; }
    float lr0 = 0.f, lr1 = 0.f;

    for (int tt=0; tt<NT; tt++){
        if (tt<NT-1){
            unsigned SKn = ((tt+1)&1)? SKb1 : SKb0;
            unsigned SVn = ((tt+1)&1)? SVb1 : SVb0;
            size_t kn = (size_t)(T0+tt+1)*128;
#pragma unroll
            for (int s=0;s<4;s++){
                unsigned so = (unsigned)(pxl[s]*QSTR + chl[s]*2);
                size_t  go = ((kn + pxl[s])*CI + chl[s])*2;
                CPA(sb+SKn+so, Kg + go);
                CPA(sb+SVn+so, Vg + go);
            }
            CP_COMMIT(); CP_WAIT(1);
        } else { CP_WAIT(0); }
        __syncthreads();

        unsigned SKc = (tt&1)? SKb1 : SKb0;
        unsigned SVc = (tt&1)? SVb1 : SVb0;

        // S = Q K^T
        float sacc[16][4];
#pragma unroll
        for (int nt=0; nt<16; nt++){ sacc[nt][0]=0.f; sacc[nt][1]=0.f; sacc[nt][2]=0.f; sacc[nt][3]=0.f; }
#pragma unroll
        for (int nt=0; nt<16; nt++){
            unsigned addr = sb + SKc + (unsigned)((nt*8 + (lane&7))*QSTR) + (unsigned)((lane>>3)*16);
            unsigned b0[4], b1[4];
            ldsm4(b0, addr);
            ldsm4(b1, addr + 64);
            mma16816(sacc[nt], aQ[0], b0[0], b0[1]);
            mma16816(sacc[nt], aQ[1], b0[2], b0[3]);
            mma16816(sacc[nt], aQ[2], b1[0], b1[1]);
            mma16816(sacc[nt], aQ[3], b1[2], b1[3]);
        }

        // exp (no max subtraction; logits bounded) + row-sum + pack P
        unsigned aP[8][4];
#pragma unroll
        for (int nt=0; nt<16; nt++){
            float e0 = __expf(sacc[nt][0]);
            float e1 = __expf(sacc[nt][1]);
            float e2 = __expf(sacc[nt][2]);
            float e3 = __expf(sacc[nt][3]);
            lr0 += e0 + e1; lr1 += e2 + e3;
            sacc[nt][0]=e0; sacc[nt][1]=e1; sacc[nt][2]=e2; sacc[nt][3]=e3;
        }
#pragma unroll
        for (int s2=0; s2<8; s2++){
            aP[s2][0] = pack_bf16x2(sacc[2*s2  ][0], sacc[2*s2  ][1]);
            aP[s2][1] = pack_bf16x2(sacc[2*s2  ][2], sacc[2*s2  ][3]);
            aP[s2][2] = pack_bf16x2(sacc[2*s2+1][0], sacc[2*s2+1][1]);
            aP[s2][3] = pack_bf16x2(sacc[2*s2+1][2], sacc[2*s2+1][3]);
        }

        // O += P V
#pragma unroll
        for (int s2=0; s2<8; s2++){
            unsigned rowa = (unsigned)((s2*16 + (lane&7) + ((lane>>3)&1)*8)*QSTR);
#pragma unroll
            for (int cp=0; cp<4; cp++){
                unsigned addr = sb + SVc + rowa + (unsigned)(cp*32 + (lane>>4)*16);
                unsigned bv[4];
                ldsm4t(bv, addr);
                mma16816(oacc[2*cp  ], aP[s2], bv[0], bv[1]);
                mma16816(oacc[2*cp+1], aP[s2], bv[2], bv[3]);
            }
        }
        __syncthreads();
    }

    // reduce row sums across the 4 lanes of each row-group
#pragma unroll
    for (int off=1; off<4; off<<=1){
        lr0 += __shfl_xor_sync(0xffffffffu, lr0, off);
        lr1 += __shfl_xor_sync(0xffffffffu, lr1, off);
    }
    int qr0 = 16*w + g, qr1 = qr0 + 8;
    if (tg==0){
        g_lsum[((size_t)ks*BB_ + b)*HW + q0 + qr0] = lr0;
        g_lsum[((size_t)ks*BB_ + b)*HW + q0 + qr1] = lr1;
    }
#pragma unroll
    for (int ct=0; ct<8; ct++){
#pragma unroll
        for (int jj=0; jj<2; jj++){
            int c = ct*8 + 2*tg + jj;
            sOut[c*132 + qr0] = oacc[ct][jj];
            sOut[c*132 + qr1] = oacc[ct][2+jj];
        }
    }
    __syncthreads();
    float* op = g_opart + (size_t)ks*BB_*CI*HW + (size_t)b*CI*HW + q0;
#pragma unroll
    for (int s=0;s<8;s++){
        int idx = tid + s*256; int c = idx>>5, p4 = (idx&31)*4;
        float4 f;
        f.x = sOut[c*132 + p4+0];
        f.y = sOut[c*132 + p4+1];
        f.z = sOut[c*132 + p4+2];
        f.w = sOut[c*132 + p4+3];
        *(float4*)(op + (size_t)c*HW + p4) = f;
    }
}

// ---------------- K4: partial Gram G = fa fa^T ----------------
__global__ __launch_bounds__(256) void kGram()
{
    __shared__ float sF[128][68]; // [n][c]
    int p0 = blockIdx.x*128, b = blockIdx.y;
    const float* fab = g_fcb + (size_t)b*CI*HW + p0;
    int tid=threadIdx.x, ty=tid>>4, tx=tid&15;
#pragma unroll
    for (int s=0;s<8;s++){
        int idx=tid+s*256; int c=idx>>5, nc=(idx&31)*4;
        float4 v = *(const float4*)(fab + (size_t)c*HW + nc);
        sF[nc+0][c]=v.x; sF[nc+1][c]=v.y; sF[nc+2][c]=v.z; sF[nc+3][c]=v.w;
    }
    __syncthreads();
    float acc[4][4];
#pragma unroll
    for (int i=0;i<4;i++)
#pragma unroll
        for (int j=0;j<4;j++) acc[i][j]=0.f;
#pragma unroll 4
    for (int n=0;n<128;n++){
        float4 a4 = *(float4*)&sF[n][ty*4];
        float4 b4 = *(float4*)&sF[n][tx*4];
        float a[4]={a4.x,a4.y,a4.z,a4.w}, bv[4]={b4.x,b4.y,b4.z,b4.w};
#pragma unroll
        for (int i=0;i<4;i++)
#pragma unroll
            for (int j=0;j<4;j++)
                acc[i][j] = fmaf(a[i], bv[j], acc[i][j]);
    }
    float* G = g_gram + b*CI*CI;
#pragma unroll
    for (int i=0;i<4;i++)
#pragma unroll
        for (int j=0;j<4;j++)
            atomicAdd(&G[(ty*4+i)*CI + tx*4+j], acc[i][j]);
}

// ---------------- K5: channel softmax of (rowmax - G) ----------------
__global__ void kSoftC()
{
    int b = blockIdx.x, c = threadIdx.x;   // block 64
    const float* G = g_gram + b*CI*CI + c*CI;
    float vmin = 1e30f;
    for (int d=0; d<CI; d++) vmin = fminf(vmin, G[d]);
    float sum = 0.f;
    for (int d=0; d<CI; d++) sum += expf(vmin - G[d]);
    float rs = 1.f/sum;
    float* A = g_attn + b*CI*CI + c*CI;
    for (int d=0; d<CI; d++) A[d] = expf(vmin - G[d])*rs;
}

// ---------------- K6 (fused kD3+kE): fusion in smem, then out conv 512x64 + BN ----------------
// grid (32 px, 4 batch), 256 thr
__global__ __launch_bounds__(256) void kDE(
    const float* __restrict__ beta, const float* __restrict__ alpha,
    const float* __restrict__ wo, const float* __restrict__ go, const float* __restrict__ bo,
    const float* __restrict__ mo, const float* __restrict__ vo, float* __restrict__ out)
{
    extern __shared__ float sm[];
    float (*sAt)[68]  = (float(*)[68])sm;               // [d][c]     17408 B
    float (*sFu)[132] = (float(*)[132])(sm + 64*68);    // fcb -> fusion tile, 33792 B
    float* sRs = sm + 64*68 + 64*132;                   // [128]
    float* sW  = sRs + 128;                             // [128][68]  34816 B
    unsigned uW = smem_u32(sW);

    int p0=blockIdx.x*128, b=blockIdx.y;
    int tid=threadIdx.x, lane=tid&31, w=tid>>5;
    int ty=tid>>4, tx=tid&15;
    int wm=w>>2, wn=w&3;

    // ---- phase 1: fusion tile ----
#pragma unroll
    for (int s=0;s<4;s++){
        int idx=tid+s*256; int c=idx>>4, dc=(idx&15)*4;
        float4 v = *(const float4*)(g_attn + b*CI*CI + c*CI + dc);
        sAt[dc+0][c]=v.x; sAt[dc+1][c]=v.y; sAt[dc+2][c]=v.z; sAt[dc+3][c]=v.w;
    }
    const float* fab = g_fcb + (size_t)b*CI*HW + p0;
#pragma unroll
    for (int s=0;s<8;s++){
        int idx=tid+s*256; int d=idx>>5, pc=(idx&31)*4;
        *(float4*)&sFu[d][pc] = *(const float4*)(fab + (size_t)d*HW + pc);
    }
    if (tid < 128){
        float l = 0.f;
#pragma unroll
        for (int ksl=0; ksl<NSPLIT; ksl++)
            l += g_lsum[((size_t)ksl*BB_ + b)*HW + p0 + tid];
        sRs[tid] = __ldg(alpha) / l;
    }
    __syncthreads();
    float acc1[4][8];
#pragma unroll
    for (int i=0;i<4;i++)
#pragma unroll
        for (int j=0;j<8;j++) acc1[i][j]=0.f;
#pragma unroll 4
    for (int d=0;d<64;d++){
        float4 a4 = *(float4*)&sAt[d][ty*4];
        float a[4]={a4.x,a4.y,a4.z,a4.w};
        float bv[8];
#pragma unroll
        for (int j=0;j<8;j++) bv[j]=sFu[d][tx*8+j];
#pragma unroll
        for (int i=0;i<4;i++)
#pragma unroll
            for (int j=0;j<8;j++)
                acc1[i][j] = fmaf(a[i], bv[j], acc1[i][j]);
    }
    __syncthreads();   // all reads of sFu (fcb) done before in-place overwrite
    float bt = __ldg(beta);
    const size_t OSZ = (size_t)BB_*CI*HW;
#pragma unroll
    for (int i=0;i<4;i++){
        int c = ty*4+i;
        size_t off = (size_t)(b*CI+c)*HW + p0 + tx*8;
#pragma unroll
        for (int h=0;h<2;h++){
            int pxb = tx*8 + h*4;
            float4 fp4  = *(const float4*)(g_fp    + off + h*4);
            float4 osum = *(const float4*)(g_opart + off + h*4);
#pragma unroll
            for (int ksl=1; ksl<NSPLIT; ksl++){
                float4 oo = *(const float4*)(g_opart + (size_t)ksl*OSZ + off + h*4);
                osum.x += oo.x; osum.y += oo.y; osum.z += oo.z; osum.w += oo.w;
            }
            float fcx = sFu[c][pxb+0], fcy = sFu[c][pxb+1], fcz = sFu[c][pxb+2], fcw = sFu[c][pxb+3];
            sFu[c][pxb+0] = fp4.x + sRs[pxb+0]*osum.x + bt*acc1[i][h*4+0] + fcx;
            sFu[c][pxb+1] = fp4.y + sRs[pxb+1]*osum.y + bt*acc1[i][h*4+1] + fcy;
            sFu[c][pxb+2] = fp4.z + sRs[pxb+2]*osum.z + bt*acc1[i][h*4+2] + fcz;
            sFu[c][pxb+3] = fp4.w + sRs[pxb+3]*osum.w + bt*acc1[i][h*4+3] + fcw;
        }
    }
    __syncthreads();

    // ---- phase 2: out conv, 4 o-blocks of 128 ----
    int orow = wm*64 + (lane>>2);
    int pxr  = wn*32 + (lane>>2);
    for (int ob=0; ob<4; ob++){
#pragma unroll
        for (int s=0;s<8;s++){
            int idx = tid + s*256;
            int o = idx>>4, kq = (idx&15)*4;
            CPA(uW + (unsigned)((o*68 + kq)*4), wo + (size_t)(ob*128+o)*CI + kq);
        }
        CP_COMMIT(); CP_WAIT(0);
        __syncthreads();

        float acc[4][4][4];
#pragma unroll
        for (int mt=0;mt<4;mt++)
#pragma unroll
            for (int nt=0;nt<4;nt++){ acc[mt][nt][0]=0.f; acc[mt][nt][1]=0.f; acc[mt][nt][2]=0.f; acc[mt][nt][3]=0.f; }

#pragma unroll
        for (int ks=0;ks<8;ks++){
            int kk = ks*8 + (lane&3);
            unsigned Ah[4][4], Al[4][4];
#pragma unroll
            for (int mt=0;mt<4;mt++){
                int ro = (orow + mt*16)*68;
                split_tf32(sW[ro+kk],        Ah[mt][0], Al[mt][0]);
                split_tf32(sW[ro+8*68+kk],   Ah[mt][1], Al[mt][1]);
                split_tf32(sW[ro+kk+4],      Ah[mt][2], Al[mt][2]);
                split_tf32(sW[ro+8*68+kk+4], Ah[mt][3], Al[mt][3]);
            }
            unsigned Bh[4][2], Bl[4][2];
#pragma unroll
            for (int nt=0;nt<4;nt++){
                split_tf32(sFu[kk][pxr + nt*8],   Bh[nt][0], Bl[nt][0]);
                split_tf32(sFu[kk+4][pxr + nt*8], Bh[nt][1], Bl[nt][1]);
            }
#pragma unroll
            for (int mt=0;mt<4;mt++)
#pragma unroll
                for (int nt=0;nt<4;nt++){
                    mma1688t(acc[mt][nt], Al[mt], Bh[nt][0], Bh[nt][1]);
                    mma1688t(acc[mt][nt], Ah[mt], Bl[nt][0], Bl[nt][1]);
                    mma1688t(acc[mt][nt], Ah[mt], Bh[nt][0], Bh[nt][1]);
                }
        }
#pragma unroll
        for (int mt=0;mt<4;mt++){
#pragma unroll
            for (int sel=0;sel<2;sel++){
                int oc = ob*128 + wm*64 + mt*16 + (lane>>2) + sel*8;
                float inv = go[oc]*rsqrtf(vo[oc]+EPS);
                float bias = bo[oc]-mo[oc]*inv;
                float* dst = out + (size_t)(b*CIN+oc)*HW;
#pragma unroll
                for (int nt=0;nt<4;nt++){
                    float2 v;
                    v.x = acc[mt][nt][sel*2+0]*inv+bias;
                    v.y = acc[mt][nt][sel*2+1]*inv+bias;
                    *(float2*)&dst[p0 + wn*32 + nt*8 + (lane&3)*2] = v;
                }
            }
        }
        __syncthreads();   // before next ob overwrites sW
    }
}

// ---------------- launch ----------------
extern "C" void kernel_launch(void* const* d_in, const int* in_sizes, int n_in,
                              void* d_out, int out_size)
{
    const float* x    = (const float*)d_in[0];
    const float* wp1  = (const float*)d_in[1];
    const float* gp1  = (const float*)d_in[2];
    const float* bp1  = (const float*)d_in[3];
    const float* mp1  = (const float*)d_in[4];
    const float* vp1  = (const float*)d_in[5];
    const float* wc1  = (const float*)d_in[6];
    const float* gc1  = (const float*)d_in[7];
    const float* bc1  = (const float*)d_in[8];
    const float* mc1  = (const float*)d_in[9];
    const float* vc1  = (const float*)d_in[10];
    const float* wb   = (const float*)d_in[11];
    const float* bb   = (const float*)d_in[12];
    const float* wc2  = (const float*)d_in[13];
    const float* bc2  = (const float*)d_in[14];
    const float* wd   = (const float*)d_in[15];
    const float* bd   = (const float*)d_in[16];
    const float* alpha= (const float*)d_in[17];
    const float* beta = (const float*)d_in[18];
    const float* wo   = (const float*)d_in[19];
    const float* go   = (const float*)d_in[20];
    const float* bo   = (const float*)d_in[21];
    const float* mo   = (const float*)d_in[22];
    const float* vo   = (const float*)d_in[23];
    float* out = (float*)d_out;

    const int SMEM_A  = 36864 + 2*16896;                       // 70656
    const int SMEM_B  = (3*64*68 + 64*132) * 4;                // 86016
    const int SMEM_C  = 73728;
    const int SMEM_DE = (64*68 + 64*132 + 128 + 128*68) * 4;   // 86528
    cudaFuncSetAttribute(kA,  cudaFuncAttributeMaxDynamicSharedMemorySize, SMEM_A);
    cudaFuncSetAttribute(kB,  cudaFuncAttributeMaxDynamicSharedMemorySize, SMEM_B);
    cudaFuncSetAttribute(kCm, cudaFuncAttributeMaxDynamicSharedMemorySize, SMEM_C);
    cudaFuncSetAttribute(kDE, cudaFuncAttributeMaxDynamicSharedMemorySize, SMEM_DE);

    kZero<<<64,256>>>();
    kA<<<dim3(32,4),256,SMEM_A>>>(x, wp1,gp1,bp1,mp1,vp1, wc1,gc1,bc1,mc1,vc1);
    kB<<<dim3(32,4),256,SMEM_B>>>(wb,bb,wc2,bc2,wd,bd);
    kCm<<<dim3(32,NSPLIT,4),256,SMEM_C>>>();
    kGram<<<dim3(32,4),256>>>();
    kSoftC<<<4,64>>>();
    kDE<<<dim3(32,4),256,SMEM_DE>>>(beta, alpha, wo,go,bo,mo,vo,out);
}

// round 13
// speedup vs baseline: 1.0008x; 1.0008x over previous
#include <cuda_runtime.h>
#include <cuda_bf16.h>
#include <math.h>

#define EPS 1e-5f
#define BB_ 4
#define CIN 512
#define CI 64
#define HW 4096
#define NSPLIT 4
#define LOG2E 1.4426950408889634f

// ---------------- scratch (device globals, no allocation) ----------------
__device__ float g_fp[BB_*CI*HW];
__device__ float g_fcb[BB_*CI*HW];
__device__ float g_gram[BB_*CI*CI];
__device__ float g_attn[BB_*CI*CI];
__device__ float g_opart[NSPLIT*BB_*CI*HW];  // partial attention O
__device__ float g_lsum[NSPLIT*BB_*HW];      // partial softmax denominators
// bf16 tensors for mma attention, all pixel-major [b][px][c]
__device__ __nv_bfloat16 g_fbt[BB_*HW*CI];   // Q (pre-scaled by log2e)
__device__ __nv_bfloat16 g_fct[BB_*HW*CI];   // K
__device__ __nv_bfloat16 g_fdt[BB_*HW*CI];   // V

// ================= PTX helpers (baseline ISA only, sm_80+) =================
static __device__ __forceinline__ unsigned smem_u32(const void* p){
    unsigned a; asm("{ .reg .u64 t; cvta.to.shared.u64 t, %1; cvt.u32.u64 %0, t; }":"=r"(a):"l"(p)); return a;
}
static __device__ __forceinline__ unsigned pack_bf16x2(float lo, float hi){
    unsigned r; asm("cvt.rn.bf16x2.f32 %0, %1, %2;" : "=r"(r) : "f"(hi), "f"(lo)); return r;
}
static __device__ __forceinline__ float ex2f(float x){
    float r; asm("ex2.approx.f32 %0, %1;" : "=f"(r) : "f"(x)); return r;
}
static __device__ __forceinline__ void ldsm4(unsigned* r, unsigned addr){
    asm volatile("ldmatrix.sync.aligned.m8n8.x4.shared.b16 {%0,%1,%2,%3}, [%4];"
        : "=r"(r[0]),"=r"(r[1]),"=r"(r[2]),"=r"(r[3]) : "r"(addr));
}
static __device__ __forceinline__ void ldsm4t(unsigned* r, unsigned addr){
    asm volatile("ldmatrix.sync.aligned.m8n8.x4.trans.shared.b16 {%0,%1,%2,%3}, [%4];"
        : "=r"(r[0]),"=r"(r[1]),"=r"(r[2]),"=r"(r[3]) : "r"(addr));
}
static __device__ __forceinline__ void mma16816(float* d, const unsigned* a, unsigned b0, unsigned b1){
    asm volatile("mma.sync.aligned.m16n8k16.row.col.f32.bf16.bf16.f32 "
        "{%0,%1,%2,%3}, {%4,%5,%6,%7}, {%8,%9}, {%0,%1,%2,%3};"
        : "+f"(d[0]),"+f"(d[1]),"+f"(d[2]),"+f"(d[3])
        : "r"(a[0]),"r"(a[1]),"r"(a[2]),"r"(a[3]), "r"(b0),"r"(b1));
}
static __device__ __forceinline__ void mma1688t(float* d, const unsigned* a, unsigned b0, unsigned b1){
    asm volatile("mma.sync.aligned.m16n8k8.row.col.f32.tf32.tf32.f32 "
        "{%0,%1,%2,%3}, {%4,%5,%6,%7}, {%8,%9}, {%0,%1,%2,%3};"
        : "+f"(d[0]),"+f"(d[1]),"+f"(d[2]),"+f"(d[3])
        : "r"(a[0]),"r"(a[1]),"r"(a[2]),"r"(a[3]), "r"(b0),"r"(b1));
}
static __device__ __forceinline__ unsigned f2t(float v){
    unsigned r; asm("cvt.rna.tf32.f32 %0, %1;" : "=r"(r) : "f"(v)); return r;
}
static __device__ __forceinline__ void split_tf32(float v, unsigned& hi, unsigned& lo){
    hi = f2t(v);
    lo = f2t(v - __uint_as_float(hi));
}
#define CPA(dst, src) asm volatile("cp.async.ca.shared.global [%0], [%1], 16;" :: "r"(dst), "l"(src))
#define CP_COMMIT()   asm volatile("cp.async.commit_group;" ::: "memory")
#define CP_WAIT(n)    asm volatile("cp.async.wait_group %0;" :: "n"(n) : "memory")

// ---------------- zero gram ----------------
__global__ void kZero() {
    int i = blockIdx.x*blockDim.x + threadIdx.x;
    if (i < BB_*CI*CI) g_gram[i] = 0.f;
}

// ---------------- K1 (tf32x3 mma): x(512) -> fp(64), fcb(64), BN fold ----------------
// tile 128o x 64px, grid (64 px-blocks, 4 batch), 256 thr, K chunks 32, double-buffered
__global__ __launch_bounds__(256) void kA(
    const float* __restrict__ x,
    const float* __restrict__ wp1, const float* __restrict__ gp1, const float* __restrict__ bp1,
    const float* __restrict__ mp1, const float* __restrict__ vp1,
    const float* __restrict__ wc1, const float* __restrict__ gc1, const float* __restrict__ bc1,
    const float* __restrict__ mc1, const float* __restrict__ vc1)
{
    extern __shared__ char smraw[];
    // W bufs [128][36] f32 (18432 B each), X bufs [32][68] f32 (8704 B each)
    float* sWf[2] = {(float*)smraw, (float*)(smraw+18432)};
    float* sXf[2] = {(float*)(smraw+36864), (float*)(smraw+36864+8704)};
    unsigned ub = smem_u32(smraw);
    unsigned uW[2] = {ub, ub+18432};
    unsigned uX[2] = {ub+36864, ub+36864+8704};

    int b = blockIdx.y, p0 = blockIdx.x*64;
    int tid=threadIdx.x, lane=tid&31, w=tid>>5;
    int wm=w>>1, wn=w&1;                   // wm 0..3 (32 o each), wn 0..1 (32 px each)
    const float* xb = x + (size_t)b*CIN*HW + p0;

    const float* wsrc[4]; unsigned wdst[4];
    const float* xsrc[2]; unsigned xdst[2]; int xk[2];
#pragma unroll
    for (int s=0;s<4;s++){
        int idx = tid + s*256;
        int o = idx>>3, kq = (idx&7)*4;        // W: 128 rows x 8 float4
        wsrc[s] = (o<64 ? wp1 + (size_t)o*CIN : wc1 + (size_t)(o-64)*CIN) + kq;
        wdst[s] = (unsigned)((o*36 + kq)*4);
    }
#pragma unroll
    for (int s=0;s<2;s++){
        int idx = tid + s*256;
        int k = idx>>4, pq = (idx&15)*4;       // X: 32 rows x 16 float4
        xk[s] = k;
        xsrc[s] = xb + pq;
        xdst[s] = (unsigned)((k*68 + pq)*4);
    }
#pragma unroll
    for (int s=0;s<4;s++) CPA(uW[0]+wdst[s], wsrc[s]);
#pragma unroll
    for (int s=0;s<2;s++) CPA(uX[0]+xdst[s], xsrc[s] + (size_t)xk[s]*HW);
    CP_COMMIT();

    float acc[2][4][4];
#pragma unroll
    for (int mt=0;mt<2;mt++)
#pragma unroll
        for (int nt=0;nt<4;nt++){ acc[mt][nt][0]=0.f; acc[mt][nt][1]=0.f; acc[mt][nt][2]=0.f; acc[mt][nt][3]=0.f; }

    int orow = wm*32 + (lane>>2);
    int pxr  = wn*32 + (lane>>2);

    for (int c=0;c<16;c++){
        if (c<15){
            int k0 = (c+1)*32; int nb=(c+1)&1;
#pragma unroll
            for (int s=0;s<4;s++) CPA(uW[nb]+wdst[s], wsrc[s]+k0);
#pragma unroll
            for (int s=0;s<2;s++) CPA(uX[nb]+xdst[s], xsrc[s] + (size_t)(k0+xk[s])*HW);
            CP_COMMIT(); CP_WAIT(1);
        } else { CP_WAIT(0); }
        __syncthreads();
        const float* Wb = sWf[c&1]; const float* Xb = sXf[c&1];
#pragma unroll
        for (int ks=0;ks<4;ks++){
            int kk = ks*8 + (lane&3);
            unsigned Ah[2][4], Al[2][4];
#pragma unroll
            for (int mt=0;mt<2;mt++){
                int ro = (orow + mt*16)*36;
                split_tf32(Wb[ro+kk],        Ah[mt][0], Al[mt][0]);
                split_tf32(Wb[ro+8*36+kk],   Ah[mt][1], Al[mt][1]);
                split_tf32(Wb[ro+kk+4],      Ah[mt][2], Al[mt][2]);
                split_tf32(Wb[ro+8*36+kk+4], Ah[mt][3], Al[mt][3]);
            }
            unsigned Bh[4][2], Bl[4][2];
#pragma unroll
            for (int nt=0;nt<4;nt++){
                split_tf32(Xb[kk*68 + pxr + nt*8],     Bh[nt][0], Bl[nt][0]);
                split_tf32(Xb[(kk+4)*68 + pxr + nt*8], Bh[nt][1], Bl[nt][1]);
            }
#pragma unroll
            for (int mt=0;mt<2;mt++)
#pragma unroll
                for (int nt=0;nt<4;nt++){
                    mma1688t(acc[mt][nt], Al[mt], Bh[nt][0], Bh[nt][1]);
                    mma1688t(acc[mt][nt], Ah[mt], Bl[nt][0], Bl[nt][1]);
                    mma1688t(acc[mt][nt], Ah[mt], Bh[nt][0], Bh[nt][1]);
                }
        }
        __syncthreads();
    }
#pragma unroll
    for (int mt=0;mt<2;mt++){
#pragma unroll
        for (int sel=0;sel<2;sel++){
            int oc = wm*32 + mt*16 + (lane>>2) + sel*8;
            float inv, bias; float* dst;
            if (oc<64){ inv=gp1[oc]*rsqrtf(vp1[oc]+EPS); bias=bp1[oc]-mp1[oc]*inv;
                        dst=g_fp+(size_t)(b*CI+oc)*HW; }
            else      { int o2=oc-64; inv=gc1[o2]*rsqrtf(vc1[o2]+EPS); bias=bc1[o2]-mc1[o2]*inv;
                        dst=g_fcb+(size_t)(b*CI+o2)*HW; }
#pragma unroll
            for (int nt=0;nt<4;nt++){
                float2 v;
                v.x = acc[mt][nt][sel*2+0]*inv+bias;
                v.y = acc[mt][nt][sel*2+1]*inv+bias;
                *(float2*)&dst[p0 + wn*32 + nt*8 + (lane&3)*2] = v;
            }
        }
    }
}

// ---------------- K2: fp(64) -> Q/K/V pixel-major bf16, 64-px tiles ----------------
// grid (64 px-blocks, 4 batch). Q (sel 0) pre-scaled by log2e for ex2 softmax.
__global__ __launch_bounds__(256) void kB(
    const float* __restrict__ wb,  const float* __restrict__ bb,
    const float* __restrict__ wc2, const float* __restrict__ bc2,
    const float* __restrict__ wd,  const float* __restrict__ bd)
{
    extern __shared__ float sm[];
    float* sW3 = sm;                                   // [3][64][68]
    float (*sF)[68] = (float(*)[68])(sm + 3*64*68);    // [k][p] 64x68
    int p0 = blockIdx.x*64, b = blockIdx.y;
    int tid=threadIdx.x, ty=tid>>4, tx=tid&15;

    const float* Ws[3] = {wb, wc2, wd};
#pragma unroll
    for (int sel=0;sel<3;sel++){
        float fac = (sel==0) ? LOG2E : 1.f;
        float* sW = sW3 + sel*64*68;
#pragma unroll
        for (int s=0;s<4;s++){
            int idx = tid + s*256;
            int j = idx>>4, cc = (idx&15)*4;
            float4 v = *(const float4*)(Ws[sel] + j*64 + cc);
            sW[(cc+0)*68+j]=v.x*fac; sW[(cc+1)*68+j]=v.y*fac; sW[(cc+2)*68+j]=v.z*fac; sW[(cc+3)*68+j]=v.w*fac;
        }
    }
    const float* fpb = g_fp + (size_t)b*CI*HW + p0;
#pragma unroll
    for (int s=0;s<4;s++){
        int idx = tid + s*256;
        int k = idx>>4, pc = (idx&15)*4;
        *(float4*)&sF[k][pc] = *(const float4*)(fpb + (size_t)k*HW + pc);
    }
    __syncthreads();
    const float* biasArr[3] = {bb, bc2, bd};
    __nv_bfloat16* dsts[3] = {g_fbt, g_fct, g_fdt};
#pragma unroll
    for (int sel=0;sel<3;sel++){
        float fac = (sel==0) ? LOG2E : 1.f;
        const float* sW = sW3 + sel*64*68;
        const float* bias = biasArr[sel];
        float acc[4][4];
#pragma unroll
        for (int i=0;i<4;i++)
#pragma unroll
            for (int j=0;j<4;j++) acc[i][j]=0.f;
        for (int k=0;k<64;k++){
            float a[4], bv[4];
#pragma unroll
            for (int i=0;i<4;i++) a[i]=sW[k*68 + ty*4+i];
#pragma unroll
            for (int j=0;j<4;j++) bv[j]=sF[k][tx*4+j];
#pragma unroll
            for (int i=0;i<4;i++)
#pragma unroll
                for (int j=0;j<4;j++)
                    acc[i][j] = fmaf(a[i], bv[j], acc[i][j]);
        }
        __nv_bfloat16* dstT = dsts[sel] + ((size_t)b*HW + p0)*CI;
        float bi0=bias[ty*4+0]*fac, bi1=bias[ty*4+1]*fac, bi2=bias[ty*4+2]*fac, bi3=bias[ty*4+3]*fac;
#pragma unroll
        for (int j=0;j<4;j++){
            uint2 v;
            v.x = pack_bf16x2(acc[0][j]+bi0, acc[1][j]+bi1);
            v.y = pack_bf16x2(acc[2][j]+bi2, acc[3][j]+bi3);
            *(uint2*)((char*)dstT + ((size_t)(tx*4+j)*CI + ty*4)*2) = v;
        }
    }
}

// ---------------- K3: mma.sync flash attention, k-split x4, cp.async double-buffered ----------------
// grid (32 q-blocks, 4 k-splits, 4 batch), 256 thr (8 warps x 16 q-rows)
#define QSTR 144   // bytes per smem row (72 bf16)
__global__ __launch_bounds__(256) void kCm()
{
    extern __shared__ char smem[];
    const int SKb0=0, SKb1=18432, SVb0=36864, SVb1=55296;   // total 73728
    float* sOut = (float*)smem;           // reused after mainloop: [64][132]
    unsigned sb = smem_u32(smem);
    int tid=threadIdx.x, lane=tid&31, w=tid>>5;
    int b=blockIdx.z, ks=blockIdx.y, q0=blockIdx.x*128;
    int g = lane>>2, tg = lane&3;
    const int NT = 32/NSPLIT;             // 8 tiles per split
    const int T0 = ks*NT;

    const char* Qg = (const char*)(g_fbt + ((size_t)b*HW + q0)*CI);
    const char* Kg = (const char*)(g_fct + (size_t)b*HW*CI);
    const char* Vg = (const char*)(g_fdt + (size_t)b*HW*CI);

    int pxl[4], chl[4];
#pragma unroll
    for (int s=0;s<4;s++){ int idx = tid + s*256; pxl[s]=idx>>3; chl[s]=(idx&7)*8; }

    // prologue: Q staged into SKb1, first K/V tile into SKb0/SVb0
#pragma unroll
    for (int s=0;s<4;s++){
        unsigned so = (unsigned)(pxl[s]*QSTR + chl[s]*2);
        size_t  go = ((size_t)pxl[s]*CI + chl[s])*2;
        size_t  gk = (((size_t)T0*128 + pxl[s])*CI + chl[s])*2;
        CPA(sb+SKb1+so, Qg + go);
        CPA(sb+SKb0+so, Kg + gk);
        CPA(sb+SVb0+so, Vg + gk);
    }
    CP_COMMIT(); CP_WAIT(0);
    __syncthreads();

    unsigned aQ[4][4];
    {
        unsigned rb = sb + SKb1 + (unsigned)((16*w + (lane&15))*QSTR) + (unsigned)((lane>>4)*16);
#pragma unroll
        for (int kq=0; kq<4; kq++) ldsm4(aQ[kq], rb + kq*32);
    }
    __syncthreads();

    float oacc[8][4];
#pragma unroll
    for (int i=0;i<8;i++){ oacc[i][0]=0.f; oacc[i][1]=0.f; oacc[i][2]=0.f; oacc[i][3]=0.f; }
    float lr0 = 0.f, lr1 = 0.f;

    for (int tt=0; tt<NT; tt++){
        if (tt<NT-1){
            unsigned SKn = ((tt+1)&1)? SKb1 : SKb0;
            unsigned SVn = ((tt+1)&1)? SVb1 : SVb0;
            size_t kn = (size_t)(T0+tt+1)*128;
#pragma unroll
            for (int s=0;s<4;s++){
                unsigned so = (unsigned)(pxl[s]*QSTR + chl[s]*2);
                size_t  go = ((kn + pxl[s])*CI + chl[s])*2;
                CPA(sb+SKn+so, Kg + go);
                CPA(sb+SVn+so, Vg + go);
            }
            CP_COMMIT(); CP_WAIT(1);
        } else { CP_WAIT(0); }
        __syncthreads();

        unsigned SKc = (tt&1)? SKb1 : SKb0;
        unsigned SVc = (tt&1)? SVb1 : SVb0;

        // S = Q K^T (Q pre-scaled by log2e)
        float sacc[16][4];
#pragma unroll
        for (int nt=0; nt<16; nt++){ sacc[nt][0]=0.f; sacc[nt][1]=0.f; sacc[nt][2]=0.f; sacc[nt][3]=0.f; }
#pragma unroll
        for (int nt=0; nt<16; nt++){
            unsigned addr = sb + SKc + (unsigned)((nt*8 + (lane&7))*QSTR) + (unsigned)((lane>>3)*16);
            unsigned b0[4], b1[4];
            ldsm4(b0, addr);
            ldsm4(b1, addr + 64);
            mma16816(sacc[nt], aQ[0], b0[0], b0[1]);
            mma16816(sacc[nt], aQ[1], b0[2], b0[3]);
            mma16816(sacc[nt], aQ[2], b1[0], b1[1]);
            mma16816(sacc[nt], aQ[3], b1[2], b1[3]);
        }

        // 2^S (== exp of unscaled logits) + row-sum + pack P
        unsigned aP[8][4];
#pragma unroll
        for (int nt=0; nt<16; nt++){
            float e0 = ex2f(sacc[nt][0]);
            float e1 = ex2f(sacc[nt][1]);
            float e2 = ex2f(sacc[nt][2]);
            float e3 = ex2f(sacc[nt][3]);
            lr0 += e0 + e1; lr1 += e2 + e3;
            sacc[nt][0]=e0; sacc[nt][1]=e1; sacc[nt][2]=e2; sacc[nt][3]=e3;
        }
#pragma unroll
        for (int s2=0; s2<8; s2++){
            aP[s2][0] = pack_bf16x2(sacc[2*s2  ][0], sacc[2*s2  ][1]);
            aP[s2][1] = pack_bf16x2(sacc[2*s2  ][2], sacc[2*s2  ][3]);
            aP[s2][2] = pack_bf16x2(sacc[2*s2+1][0], sacc[2*s2+1][1]);
            aP[s2][3] = pack_bf16x2(sacc[2*s2+1][2], sacc[2*s2+1][3]);
        }

        // O += P V
#pragma unroll
        for (int s2=0; s2<8; s2++){
            unsigned rowa = (unsigned)((s2*16 + (lane&7) + ((lane>>3)&1)*8)*QSTR);
#pragma unroll
            for (int cp=0; cp<4; cp++){
                unsigned addr = sb + SVc + rowa + (unsigned)(cp*32 + (lane>>4)*16);
                unsigned bv[4];
                ldsm4t(bv, addr);
                mma16816(oacc[2*cp  ], aP[s2], bv[0], bv[1]);
                mma16816(oacc[2*cp+1], aP[s2], bv[2], bv[3]);
            }
        }
        __syncthreads();
    }

#pragma unroll
    for (int off=1; off<4; off<<=1){
        lr0 += __shfl_xor_sync(0xffffffffu, lr0, off);
        lr1 += __shfl_xor_sync(0xffffffffu, lr1, off);
    }
    int qr0 = 16*w + g, qr1 = qr0 + 8;
    if (tg==0){
        g_lsum[((size_t)ks*BB_ + b)*HW + q0 + qr0] = lr0;
        g_lsum[((size_t)ks*BB_ + b)*HW + q0 + qr1] = lr1;
    }
#pragma unroll
    for (int ct=0; ct<8; ct++){
#pragma unroll
        for (int jj=0; jj<2; jj++){
            int c = ct*8 + 2*tg + jj;
            sOut[c*132 + qr0] = oacc[ct][jj];
            sOut[c*132 + qr1] = oacc[ct][2+jj];
        }
    }
    __syncthreads();
    float* op = g_opart + (size_t)ks*BB_*CI*HW + (size_t)b*CI*HW + q0;
#pragma unroll
    for (int s=0;s<8;s++){
        int idx = tid + s*256; int c = idx>>5, p4 = (idx&31)*4;
        float4 f;
        f.x = sOut[c*132 + p4+0];
        f.y = sOut[c*132 + p4+1];
        f.z = sOut[c*132 + p4+2];
        f.w = sOut[c*132 + p4+3];
        *(float4*)(op + (size_t)c*HW + p4) = f;
    }
}

// ---------------- K4: partial Gram G = fa fa^T, 64-px chunks ----------------
__global__ __launch_bounds__(256) void kGram()
{
    __shared__ float sF[64][68]; // [n][c]
    int p0 = blockIdx.x*64, b = blockIdx.y;
    const float* fab = g_fcb + (size_t)b*CI*HW + p0;
    int tid=threadIdx.x, ty=tid>>4, tx=tid&15;
#pragma unroll
    for (int s=0;s<4;s++){
        int idx=tid+s*256; int c=idx>>4, nc=(idx&15)*4;
        float4 v = *(const float4*)(fab + (size_t)c*HW + nc);
        sF[nc+0][c]=v.x; sF[nc+1][c]=v.y; sF[nc+2][c]=v.z; sF[nc+3][c]=v.w;
    }
    __syncthreads();
    float acc[4][4];
#pragma unroll
    for (int i=0;i<4;i++)
#pragma unroll
        for (int j=0;j<4;j++) acc[i][j]=0.f;
#pragma unroll 4
    for (int n=0;n<64;n++){
        float4 a4 = *(float4*)&sF[n][ty*4];
        float4 b4 = *(float4*)&sF[n][tx*4];
        float a[4]={a4.x,a4.y,a4.z,a4.w}, bv[4]={b4.x,b4.y,b4.z,b4.w};
#pragma unroll
        for (int i=0;i<4;i++)
#pragma unroll
            for (int j=0;j<4;j++)
                acc[i][j] = fmaf(a[i], bv[j], acc[i][j]);
    }
    float* G = g_gram + b*CI*CI;
#pragma unroll
    for (int i=0;i<4;i++)
#pragma unroll
        for (int j=0;j<4;j++)
            atomicAdd(&G[(ty*4+i)*CI + tx*4+j], acc[i][j]);
}

// ---------------- K5: channel softmax of (rowmax - G) ----------------
__global__ void kSoftC()
{
    int b = blockIdx.x, c = threadIdx.x;   // block 64
    const float* G = g_gram + b*CI*CI + c*CI;
    float vmin = 1e30f;
    for (int d=0; d<CI; d++) vmin = fminf(vmin, G[d]);
    float sum = 0.f;
    for (int d=0; d<CI; d++) sum += expf(vmin - G[d]);
    float rs = 1.f/sum;
    float* A = g_attn + b*CI*CI + c*CI;
    for (int d=0; d<CI; d++) A[d] = expf(vmin - G[d])*rs;
}

// ---------------- K6 (fused): fusion tile in smem, then out conv 512x64 + BN ----------------
// 64-px tiles, grid (64 px, 4 batch), 256 thr
__global__ __launch_bounds__(256) void kDE(
    const float* __restrict__ beta, const float* __restrict__ alpha,
    const float* __restrict__ wo, const float* __restrict__ go, const float* __restrict__ bo,
    const float* __restrict__ mo, const float* __restrict__ vo, float* __restrict__ out)
{
    extern __shared__ float sm[];
    float (*sAt)[68] = (float(*)[68])sm;                // [d][c]    17408 B
    float (*sFu)[68] = (float(*)[68])(sm + 64*68);      // fcb -> fusion tile [64ch][64px+pad]
    float* sRs = sm + 2*64*68;                          // [64]
    float* sW  = sRs + 64;                              // [128][68]  34816 B
    unsigned uW = smem_u32(sW);

    int p0=blockIdx.x*64, b=blockIdx.y;
    int tid=threadIdx.x, lane=tid&31, w=tid>>5;
    int ty=tid>>4, tx=tid&15;
    int wm=w>>1, wn=w&1;

    // ---- phase 1: fusion tile ----
#pragma unroll
    for (int s=0;s<4;s++){
        int idx=tid+s*256; int c=idx>>4, dc=(idx&15)*4;
        float4 v = *(const float4*)(g_attn + b*CI*CI + c*CI + dc);
        sAt[dc+0][c]=v.x; sAt[dc+1][c]=v.y; sAt[dc+2][c]=v.z; sAt[dc+3][c]=v.w;
    }
    const float* fab = g_fcb + (size_t)b*CI*HW + p0;
#pragma unroll
    for (int s=0;s<4;s++){
        int idx=tid+s*256; int d=idx>>4, pc=(idx&15)*4;
        *(float4*)&sFu[d][pc] = *(const float4*)(fab + (size_t)d*HW + pc);
    }
    if (tid < 64){
        float l = 0.f;
#pragma unroll
        for (int ksl=0; ksl<NSPLIT; ksl++)
            l += g_lsum[((size_t)ksl*BB_ + b)*HW + p0 + tid];
        sRs[tid] = __ldg(alpha) / l;
    }
    __syncthreads();
    float acc1[4][4];
#pragma unroll
    for (int i=0;i<4;i++)
#pragma unroll
        for (int j=0;j<4;j++) acc1[i][j]=0.f;
#pragma unroll 4
    for (int d=0;d<64;d++){
        float4 a4 = *(float4*)&sAt[d][ty*4];
        float a[4]={a4.x,a4.y,a4.z,a4.w};
        float4 b4 = *(float4*)&sFu[d][tx*4];
        float bv[4]={b4.x,b4.y,b4.z,b4.w};
#pragma unroll
        for (int i=0;i<4;i++)
#pragma unroll
            for (int j=0;j<4;j++)
                acc1[i][j] = fmaf(a[i], bv[j], acc1[i][j]);
    }
    __syncthreads();   // all fcb reads done before in-place overwrite
    float bt = __ldg(beta);
    const size_t OSZ = (size_t)BB_*CI*HW;
#pragma unroll
    for (int i=0;i<4;i++){
        int c = ty*4+i;
        int pxb = tx*4;
        size_t off = (size_t)(b*CI+c)*HW + p0 + pxb;
        float4 fp4  = *(const float4*)(g_fp    + off);
        float4 osum = *(const float4*)(g_opart + off);
#pragma unroll
        for (int ksl=1; ksl<NSPLIT; ksl++){
            float4 oo = *(const float4*)(g_opart + (size_t)ksl*OSZ + off);
            osum.x += oo.x; osum.y += oo.y; osum.z += oo.z; osum.w += oo.w;
        }
        float fcx = sFu[c][pxb+0], fcy = sFu[c][pxb+1], fcz = sFu[c][pxb+2], fcw = sFu[c][pxb+3];
        sFu[c][pxb+0] = fp4.x + sRs[pxb+0]*osum.x + bt*acc1[i][0] + fcx;
        sFu[c][pxb+1] = fp4.y + sRs[pxb+1]*osum.y + bt*acc1[i][1] + fcy;
        sFu[c][pxb+2] = fp4.z + sRs[pxb+2]*osum.z + bt*acc1[i][2] + fcz;
        sFu[c][pxb+3] = fp4.w + sRs[pxb+3]*osum.w + bt*acc1[i][3] + fcw;
    }
    __syncthreads();

    // ---- phase 2: out conv, 4 o-blocks of 128 ----
    int orow = wm*32 + (lane>>2);
    int pxr  = wn*32 + (lane>>2);
    for (int ob=0; ob<4; ob++){
#pragma unroll
        for (int s=0;s<8;s++){
            int idx = tid + s*256;
            int o = idx>>4, kq = (idx&15)*4;
            CPA(uW + (unsigned)((o*68 + kq)*4), wo + (size_t)(ob*128+o)*CI + kq);
        }
        CP_COMMIT(); CP_WAIT(0);
        __syncthreads();

        float acc[2][4][4];
#pragma unroll
        for (int mt=0;mt<2;mt++)
#pragma unroll
            for (int nt=0;nt<4;nt++){ acc[mt][nt][0]=0.f; acc[mt][nt][1]=0.f; acc[mt][nt][2]=0.f; acc[mt][nt][3]=0.f; }

#pragma unroll
        for (int ks=0;ks<8;ks++){
            int kk = ks*8 + (lane&3);
            unsigned Ah[2][4], Al[2][4];
#pragma unroll
            for (int mt=0;mt<2;mt++){
                int ro = (orow + mt*16)*68;
                split_tf32(sW[ro+kk],        Ah[mt][0], Al[mt][0]);
                split_tf32(sW[ro+8*68+kk],   Ah[mt][1], Al[mt][1]);
                split_tf32(sW[ro+kk+4],      Ah[mt][2], Al[mt][2]);
                split_tf32(sW[ro+8*68+kk+4], Ah[mt][3], Al[mt][3]);
            }
            unsigned Bh[4][2], Bl[4][2];
#pragma unroll
            for (int nt=0;nt<4;nt++){
                split_tf32(sFu[kk][pxr + nt*8],   Bh[nt][0], Bl[nt][0]);
                split_tf32(sFu[kk+4][pxr + nt*8], Bh[nt][1], Bl[nt][1]);
            }
#pragma unroll
            for (int mt=0;mt<2;mt++)
#pragma unroll
                for (int nt=0;nt<4;nt++){
                    mma1688t(acc[mt][nt], Al[mt], Bh[nt][0], Bh[nt][1]);
                    mma1688t(acc[mt][nt], Ah[mt], Bl[nt][0], Bl[nt][1]);
                    mma1688t(acc[mt][nt], Ah[mt], Bh[nt][0], Bh[nt][1]);
                }
        }
#pragma unroll
        for (int mt=0;mt<2;mt++){
#pragma unroll
            for (int sel=0;sel<2;sel++){
                int oc = ob*128 + wm*32 + mt*16 + (lane>>2) + sel*8;
                float inv = go[oc]*rsqrtf(vo[oc]+EPS);
                float bias = bo[oc]-mo[oc]*inv;
                float* dst = out + (size_t)(b*CIN+oc)*HW;
#pragma unroll
                for (int nt=0;nt<4;nt++){
                    float2 v;
                    v.x = acc[mt][nt][sel*2+0]*inv+bias;
                    v.y = acc[mt][nt][sel*2+1]*inv+bias;
                    *(float2*)&dst[p0 + wn*32 + nt*8 + (lane&3)*2] = v;
                }
            }
        }
        __syncthreads();   // before next ob overwrites sW
    }
}

// ---------------- launch ----------------
extern "C" void kernel_launch(void* const* d_in, const int* in_sizes, int n_in,
                              void* d_out, int out_size)
{
    const float* x    = (const float*)d_in[0];
    const float* wp1  = (const float*)d_in[1];
    const float* gp1  = (const float*)d_in[2];
    const float* bp1  = (const float*)d_in[3];
    const float* mp1  = (const float*)d_in[4];
    const float* vp1  = (const float*)d_in[5];
    const float* wc1  = (const float*)d_in[6];
    const float* gc1  = (const float*)d_in[7];
    const float* bc1  = (const float*)d_in[8];
    const float* mc1  = (const float*)d_in[9];
    const float* vc1  = (const float*)d_in[10];
    const float* wb   = (const float*)d_in[11];
    const float* bb   = (const float*)d_in[12];
    const float* wc2  = (const float*)d_in[13];
    const float* bc2  = (const float*)d_in[14];
    const float* wd   = (const float*)d_in[15];
    const float* bd   = (const float*)d_in[16];
    const float* alpha= (const float*)d_in[17];
    const float* beta = (const float*)d_in[18];
    const float* wo   = (const float*)d_in[19];
    const float* go   = (const float*)d_in[20];
    const float* bo   = (const float*)d_in[21];
    const float* mo   = (const float*)d_in[22];
    const float* vo   = (const float*)d_in[23];
    float* out = (float*)d_out;

    const int SMEM_A  = 36864 + 2*8704;                   // 54272
    const int SMEM_B  = (3*64*68 + 64*68) * 4;            // 69632
    const int SMEM_C  = 73728;
    const int SMEM_DE = (2*64*68 + 64 + 128*68) * 4;      // 69888
    cudaFuncSetAttribute(kA,  cudaFuncAttributeMaxDynamicSharedMemorySize, SMEM_A);
    cudaFuncSetAttribute(kB,  cudaFuncAttributeMaxDynamicSharedMemorySize, SMEM_B);
    cudaFuncSetAttribute(kCm, cudaFuncAttributeMaxDynamicSharedMemorySize, SMEM_C);
    cudaFuncSetAttribute(kDE, cudaFuncAttributeMaxDynamicSharedMemorySize, SMEM_DE);

    kZero<<<64,256>>>();
    kA<<<dim3(64,4),256,SMEM_A>>>(x, wp1,gp1,bp1,mp1,vp1, wc1,gc1,bc1,mc1,vc1);
    kB<<<dim3(64,4),256,SMEM_B>>>(wb,bb,wc2,bc2,wd,bd);
    kCm<<<dim3(32,NSPLIT,4),256,SMEM_C>>>();
    kGram<<<dim3(64,4),256>>>();
    kSoftC<<<4,64>>>();
    kDE<<<dim3(64,4),256,SMEM_DE>>>(beta, alpha, wo,go,bo,mo,vo,out);
}

// round 15
// speedup vs baseline: 1.2258x; 1.2248x over previous
#include <cuda_runtime.h>
#include <cuda_bf16.h>
#include <math.h>

#define EPS 1e-5f
#define BB_ 4
#define CIN 512
#define CI 64
#define HW 4096
#define NSPLIT 4
#define LOG2E 1.4426950408889634f

// ---------------- scratch (device globals, no allocation) ----------------
__device__ float g_fp[BB_*CI*HW];
__device__ float g_fcb[BB_*CI*HW];
__device__ float g_gram[BB_*CI*CI];
__device__ float g_opart[NSPLIT*BB_*CI*HW];  // partial attention O
__device__ float g_lsum[NSPLIT*BB_*HW];      // partial softmax denominators
// bf16 tensors for mma attention, all pixel-major [b][px][c]
__device__ __nv_bfloat16 g_fbt[BB_*HW*CI];   // Q (pre-scaled by log2e)
__device__ __nv_bfloat16 g_fct[BB_*HW*CI];   // K
__device__ __nv_bfloat16 g_fdt[BB_*HW*CI];   // V

// ================= PTX helpers (baseline ISA only, sm_80+) =================
static __device__ __forceinline__ unsigned smem_u32(const void* p){
    unsigned a; asm("{ .reg .u64 t; cvta.to.shared.u64 t, %1; cvt.u32.u64 %0, t; }":"=r"(a):"l"(p)); return a;
}
static __device__ __forceinline__ unsigned pack_bf16x2(float lo, float hi){
    unsigned r; asm("cvt.rn.bf16x2.f32 %0, %1, %2;" : "=r"(r) : "f"(hi), "f"(lo)); return r;
}
static __device__ __forceinline__ float ex2f(float x){
    float r; asm("ex2.approx.f32 %0, %1;" : "=f"(r) : "f"(x)); return r;
}
static __device__ __forceinline__ void ldsm4(unsigned* r, unsigned addr){
    asm volatile("ldmatrix.sync.aligned.m8n8.x4.shared.b16 {%0,%1,%2,%3}, [%4];"
        : "=r"(r[0]),"=r"(r[1]),"=r"(r[2]),"=r"(r[3]) : "r"(addr));
}
static __device__ __forceinline__ void ldsm4t(unsigned* r, unsigned addr){
    asm volatile("ldmatrix.sync.aligned.m8n8.x4.trans.shared.b16 {%0,%1,%2,%3}, [%4];"
        : "=r"(r[0]),"=r"(r[1]),"=r"(r[2]),"=r"(r[3]) : "r"(addr));
}
static __device__ __forceinline__ void mma16816(float* d, const unsigned* a, unsigned b0, unsigned b1){
    asm volatile("mma.sync.aligned.m16n8k16.row.col.f32.bf16.bf16.f32 "
        "{%0,%1,%2,%3}, {%4,%5,%6,%7}, {%8,%9}, {%0,%1,%2,%3};"
        : "+f"(d[0]),"+f"(d[1]),"+f"(d[2]),"+f"(d[3])
        : "r"(a[0]),"r"(a[1]),"r"(a[2]),"r"(a[3]), "r"(b0),"r"(b1));
}
// split-precision bf16: v = hi + lo, hi = truncate-to-bf16(v)
// packs pairs (v0=k, v1=k+1) into fragment regs: low half = k, high = k+1
static __device__ __forceinline__ void split_bf16x2(float v0, float v1, unsigned& hi, unsigned& lo){
    unsigned u0 = __float_as_uint(v0), u1 = __float_as_uint(v1);
    asm("prmt.b32 %0, %1, %2, 0x7632;" : "=r"(hi) : "r"(u0), "r"(u1));
    float l0 = v0 - __uint_as_float(u0 & 0xFFFF0000u);
    float l1 = v1 - __uint_as_float(u1 & 0xFFFF0000u);
    lo = pack_bf16x2(l0, l1);
}
#define CPA(dst, src) asm volatile("cp.async.ca.shared.global [%0], [%1], 16;" :: "r"(dst), "l"(src))
#define CP_COMMIT()   asm volatile("cp.async.commit_group;" ::: "memory")
#define CP_WAIT(n)    asm volatile("cp.async.wait_group %0;" :: "n"(n) : "memory")

// ---------------- K1 (bf16x3 mma): x(512) -> fp(64), fcb(64), BN fold ----------------
// tile 128o x 64px, grid (64 px-blocks, 4 batch), 256 thr, K chunks 32, double-buffered
__global__ __launch_bounds__(256) void kA(
    const float* __restrict__ x,
    const float* __restrict__ wp1, const float* __restrict__ gp1, const float* __restrict__ bp1,
    const float* __restrict__ mp1, const float* __restrict__ vp1,
    const float* __restrict__ wc1, const float* __restrict__ gc1, const float* __restrict__ bc1,
    const float* __restrict__ mc1, const float* __restrict__ vc1)
{
    extern __shared__ char smraw[];
    float* sWf[2] = {(float*)smraw, (float*)(smraw+18432)};
    float* sXf[2] = {(float*)(smraw+36864), (float*)(smraw+36864+8704)};
    unsigned ub = smem_u32(smraw);
    unsigned uW[2] = {ub, ub+18432};
    unsigned uX[2] = {ub+36864, ub+36864+8704};

    int b = blockIdx.y, p0 = blockIdx.x*64;
    int tid=threadIdx.x, lane=tid&31, w=tid>>5;
    int wm=w>>1, wn=w&1;
    const float* xb = x + (size_t)b*CIN*HW + p0;

    const float* wsrc[4]; unsigned wdst[4];
    const float* xsrc[2]; unsigned xdst[2]; int xk[2];
#pragma unroll
    for (int s=0;s<4;s++){
        int idx = tid + s*256;
        int o = idx>>3, kq = (idx&7)*4;
        wsrc[s] = (o<64 ? wp1 + (size_t)o*CIN : wc1 + (size_t)(o-64)*CIN) + kq;
        wdst[s] = (unsigned)((o*36 + kq)*4);
    }
#pragma unroll
    for (int s=0;s<2;s++){
        int idx = tid + s*256;
        int k = idx>>4, pq = (idx&15)*4;
        xk[s] = k;
        xsrc[s] = xb + pq;
        xdst[s] = (unsigned)((k*68 + pq)*4);
    }
#pragma unroll
    for (int s=0;s<4;s++) CPA(uW[0]+wdst[s], wsrc[s]);
#pragma unroll
    for (int s=0;s<2;s++) CPA(uX[0]+xdst[s], xsrc[s] + (size_t)xk[s]*HW);
    CP_COMMIT();

    float acc[2][4][4];
#pragma unroll
    for (int mt=0;mt<2;mt++)
#pragma unroll
        for (int nt=0;nt<4;nt++){ acc[mt][nt][0]=0.f; acc[mt][nt][1]=0.f; acc[mt][nt][2]=0.f; acc[mt][nt][3]=0.f; }

    int orow = wm*32 + (lane>>2);
    int pxr  = wn*32 + (lane>>2);

    for (int c=0;c<16;c++){
        if (c<15){
            int k0 = (c+1)*32; int nb=(c+1)&1;
#pragma unroll
            for (int s=0;s<4;s++) CPA(uW[nb]+wdst[s], wsrc[s]+k0);
#pragma unroll
            for (int s=0;s<2;s++) CPA(uX[nb]+xdst[s], xsrc[s] + (size_t)(k0+xk[s])*HW);
            CP_COMMIT(); CP_WAIT(1);
        } else { CP_WAIT(0); }
        __syncthreads();
        const float* Wb = sWf[c&1]; const float* Xb = sXf[c&1];
#pragma unroll
        for (int kst=0;kst<2;kst++){
            int kk2 = kst*16 + (lane&3)*2;
            unsigned Ah[2][4], Al[2][4];
#pragma unroll
            for (int mt=0;mt<2;mt++){
                int ro = (orow + mt*16)*36;
                float2 p0 = *(const float2*)&Wb[ro + kk2];
                float2 p1 = *(const float2*)&Wb[ro + 8*36 + kk2];
                float2 p2 = *(const float2*)&Wb[ro + kk2 + 8];
                float2 p3 = *(const float2*)&Wb[ro + 8*36 + kk2 + 8];
                split_bf16x2(p0.x, p0.y, Ah[mt][0], Al[mt][0]);
                split_bf16x2(p1.x, p1.y, Ah[mt][1], Al[mt][1]);
                split_bf16x2(p2.x, p2.y, Ah[mt][2], Al[mt][2]);
                split_bf16x2(p3.x, p3.y, Ah[mt][3], Al[mt][3]);
            }
            unsigned Bh[4][2], Bl[4][2];
#pragma unroll
            for (int nt=0;nt<4;nt++){
                int col = pxr + nt*8;
                split_bf16x2(Xb[(kk2  )*68 + col], Xb[(kk2+1)*68 + col], Bh[nt][0], Bl[nt][0]);
                split_bf16x2(Xb[(kk2+8)*68 + col], Xb[(kk2+9)*68 + col], Bh[nt][1], Bl[nt][1]);
            }
#pragma unroll
            for (int mt=0;mt<2;mt++)
#pragma unroll
                for (int nt=0;nt<4;nt++){
                    mma16816(acc[mt][nt], Al[mt], Bh[nt][0], Bh[nt][1]);
                    mma16816(acc[mt][nt], Ah[mt], Bl[nt][0], Bl[nt][1]);
                    mma16816(acc[mt][nt], Ah[mt], Bh[nt][0], Bh[nt][1]);
                }
        }
        __syncthreads();
    }
#pragma unroll
    for (int mt=0;mt<2;mt++){
#pragma unroll
        for (int sel=0;sel<2;sel++){
            int oc = wm*32 + mt*16 + (lane>>2) + sel*8;
            float inv, bias; float* dst;
            if (oc<64){ inv=gp1[oc]*rsqrtf(vp1[oc]+EPS); bias=bp1[oc]-mp1[oc]*inv;
                        dst=g_fp+(size_t)(b*CI+oc)*HW; }
            else      { int o2=oc-64; inv=gc1[o2]*rsqrtf(vc1[o2]+EPS); bias=bc1[o2]-mc1[o2]*inv;
                        dst=g_fcb+(size_t)(b*CI+o2)*HW; }
#pragma unroll
            for (int nt=0;nt<4;nt++){
                float2 v;
                v.x = acc[mt][nt][sel*2+0]*inv+bias;
                v.y = acc[mt][nt][sel*2+1]*inv+bias;
                *(float2*)&dst[p0 + wn*32 + nt*8 + (lane&3)*2] = v;
            }
        }
    }
}

// ---------------- K2: fp(64) -> Q/K/V pixel-major bf16, 64-px tiles ----------------
// also zeroes g_gram (must run before kGram; stream order guarantees)
__global__ __launch_bounds__(256) void kB(
    const float* __restrict__ wb,  const float* __restrict__ bb,
    const float* __restrict__ wc2, const float* __restrict__ bc2,
    const float* __restrict__ wd,  const float* __restrict__ bd)
{
    extern __shared__ float sm[];
    float* sW3 = sm;                                   // [3][64][68]
    float (*sF)[68] = (float(*)[68])(sm + 3*64*68);    // [k][p]
    int p0 = blockIdx.x*64, b = blockIdx.y;
    int tid=threadIdx.x, ty=tid>>4, tx=tid&15;

    // zero gram: 256 CTAs x 64 floats = 16384
    if (tid < 64) g_gram[(blockIdx.y*64 + blockIdx.x)*64 + tid] = 0.f;

    const float* Ws[3] = {wb, wc2, wd};
#pragma unroll
    for (int sel=0;sel<3;sel++){
        float fac = (sel==0) ? LOG2E : 1.f;
        float* sW = sW3 + sel*64*68;
#pragma unroll
        for (int s=0;s<4;s++){
            int idx = tid + s*256;
            int j = idx>>4, cc = (idx&15)*4;
            float4 v = *(const float4*)(Ws[sel] + j*64 + cc);
            sW[(cc+0)*68+j]=v.x*fac; sW[(cc+1)*68+j]=v.y*fac; sW[(cc+2)*68+j]=v.z*fac; sW[(cc+3)*68+j]=v.w*fac;
        }
    }
    const float* fpb = g_fp + (size_t)b*CI*HW + p0;
#pragma unroll
    for (int s=0;s<4;s++){
        int idx = tid + s*256;
        int k = idx>>4, pc = (idx&15)*4;
        *(float4*)&sF[k][pc] = *(const float4*)(fpb + (size_t)k*HW + pc);
    }
    __syncthreads();
    const float* biasArr[3] = {bb, bc2, bd};
    __nv_bfloat16* dsts[3] = {g_fbt, g_fct, g_fdt};
#pragma unroll
    for (int sel=0;sel<3;sel++){
        float fac = (sel==0) ? LOG2E : 1.f;
        const float* sW = sW3 + sel*64*68;
        const float* bias = biasArr[sel];
        float acc[4][4];
#pragma unroll
        for (int i=0;i<4;i++)
#pragma unroll
            for (int j=0;j<4;j++) acc[i][j]=0.f;
        for (int k=0;k<64;k++){
            float a[4], bv[4];
#pragma unroll
            for (int i=0;i<4;i++) a[i]=sW[k*68 + ty*4+i];
#pragma unroll
            for (int j=0;j<4;j++) bv[j]=sF[k][tx*4+j];
#pragma unroll
            for (int i=0;i<4;i++)
#pragma unroll
                for (int j=0;j<4;j++)
                    acc[i][j] = fmaf(a[i], bv[j], acc[i][j]);
        }
        __nv_bfloat16* dstT = dsts[sel] + ((size_t)b*HW + p0)*CI;
        float bi0=bias[ty*4+0]*fac, bi1=bias[ty*4+1]*fac, bi2=bias[ty*4+2]*fac, bi3=bias[ty*4+3]*fac;
#pragma unroll
        for (int j=0;j<4;j++){
            uint2 v;
            v.x = pack_bf16x2(acc[0][j]+bi0, acc[1][j]+bi1);
            v.y = pack_bf16x2(acc[2][j]+bi2, acc[3][j]+bi3);
            *(uint2*)((char*)dstT + ((size_t)(tx*4+j)*CI + ty*4)*2) = v;
        }
    }
}

// ---------------- K3: mma.sync flash attention, k-split x4, cp.async double-buffered ----------------
#define QSTR 144   // bytes per smem row (72 bf16)
__global__ __launch_bounds__(256) void kCm()
{
    extern __shared__ char smem[];
    const int SKb0=0, SKb1=18432, SVb0=36864, SVb1=55296;
    float* sOut = (float*)smem;
    unsigned sb = smem_u32(smem);
    int tid=threadIdx.x, lane=tid&31, w=tid>>5;
    int b=blockIdx.z, ks=blockIdx.y, q0=blockIdx.x*128;
    int g = lane>>2, tg = lane&3;
    const int NT = 32/NSPLIT;
    const int T0 = ks*NT;

    const char* Qg = (const char*)(g_fbt + ((size_t)b*HW + q0)*CI);
    const char* Kg = (const char*)(g_fct + (size_t)b*HW*CI);
    const char* Vg = (const char*)(g_fdt + (size_t)b*HW*CI);

    int pxl[4], chl[4];
#pragma unroll
    for (int s=0;s<4;s++){ int idx = tid + s*256; pxl[s]=idx>>3; chl[s]=(idx&7)*8; }

#pragma unroll
    for (int s=0;s<4;s++){
        unsigned so = (unsigned)(pxl[s]*QSTR + chl[s]*2);
        size_t  go = ((size_t)pxl[s]*CI + chl[s])*2;
        size_t  gk = (((size_t)T0*128 + pxl[s])*CI + chl[s])*2;
        CPA(sb+SKb1+so, Qg + go);
        CPA(sb+SKb0+so, Kg + gk);
        CPA(sb+SVb0+so, Vg + gk);
    }
    CP_COMMIT(); CP_WAIT(0);
    __syncthreads();

    unsigned aQ[4][4];
    {
        unsigned rb = sb + SKb1 + (unsigned)((16*w + (lane&15))*QSTR) + (unsigned)((lane>>4)*16);
#pragma unroll
        for (int kq=0; kq<4; kq++) ldsm4(aQ[kq], rb + kq*32);
    }
    __syncthreads();

    float oacc[8][4];
#pragma unroll
    for (int i=0;i<8;i++){ oacc[i][0]=0.f; oacc[i][1]=0.f; oacc[i][2]=0.f; oacc[i][3]=0.f; }
    float lr0 = 0.f, lr1 = 0.f;

    for (int tt=0; tt<NT; tt++){
        if (tt<NT-1){
            unsigned SKn = ((tt+1)&1)? SKb1 : SKb0;
            unsigned SVn = ((tt+1)&1)? SVb1 : SVb0;
            size_t kn = (size_t)(T0+tt+1)*128;
#pragma unroll
            for (int s=0;s<4;s++){
                unsigned so = (unsigned)(pxl[s]*QSTR + chl[s]*2);
                size_t  go = ((kn + pxl[s])*CI + chl[s])*2;
                CPA(sb+SKn+so, Kg + go);
                CPA(sb+SVn+so, Vg + go);
            }
            CP_COMMIT(); CP_WAIT(1);
        } else { CP_WAIT(0); }
        __syncthreads();

        unsigned SKc = (tt&1)? SKb1 : SKb0;
        unsigned SVc = (tt&1)? SVb1 : SVb0;

        float sacc[16][4];
#pragma unroll
        for (int nt=0; nt<16; nt++){ sacc[nt][0]=0.f; sacc[nt][1]=0.f; sacc[nt][2]=0.f; sacc[nt][3]=0.f; }
#pragma unroll
        for (int nt=0; nt<16; nt++){
            unsigned addr = sb + SKc + (unsigned)((nt*8 + (lane&7))*QSTR) + (unsigned)((lane>>3)*16);
            unsigned b0[4], b1[4];
            ldsm4(b0, addr);
            ldsm4(b1, addr + 64);
            mma16816(sacc[nt], aQ[0], b0[0], b0[1]);
            mma16816(sacc[nt], aQ[1], b0[2], b0[3]);
            mma16816(sacc[nt], aQ[2], b1[0], b1[1]);
            mma16816(sacc[nt], aQ[3], b1[2], b1[3]);
        }

        unsigned aP[8][4];
#pragma unroll
        for (int nt=0; nt<16; nt++){
            float e0 = ex2f(sacc[nt][0]);
            float e1 = ex2f(sacc[nt][1]);
            float e2 = ex2f(sacc[nt][2]);
            float e3 = ex2f(sacc[nt][3]);
            lr0 += e0 + e1; lr1 += e2 + e3;
            sacc[nt][0]=e0; sacc[nt][1]=e1; sacc[nt][2]=e2; sacc[nt][3]=e3;
        }
#pragma unroll
        for (int s2=0; s2<8; s2++){
            aP[s2][0] = pack_bf16x2(sacc[2*s2  ][0], sacc[2*s2  ][1]);
            aP[s2][1] = pack_bf16x2(sacc[2*s2  ][2], sacc[2*s2  ][3]);
            aP[s2][2] = pack_bf16x2(sacc[2*s2+1][0], sacc[2*s2+1][1]);
            aP[s2][3] = pack_bf16x2(sacc[2*s2+1][2], sacc[2*s2+1][3]);
        }

#pragma unroll
        for (int s2=0; s2<8; s2++){
            unsigned rowa = (unsigned)((s2*16 + (lane&7) + ((lane>>3)&1)*8)*QSTR);
#pragma unroll
            for (int cp=0; cp<4; cp++){
                unsigned addr = sb + SVc + rowa + (unsigned)(cp*32 + (lane>>4)*16);
                unsigned bv[4];
                ldsm4t(bv, addr);
                mma16816(oacc[2*cp  ], aP[s2], bv[0], bv[1]);
                mma16816(oacc[2*cp+1], aP[s2], bv[2], bv[3]);
            }
        }
        __syncthreads();
    }

#pragma unroll
    for (int off=1; off<4; off<<=1){
        lr0 += __shfl_xor_sync(0xffffffffu, lr0, off);
        lr1 += __shfl_xor_sync(0xffffffffu, lr1, off);
    }
    int qr0 = 16*w + g, qr1 = qr0 + 8;
    if (tg==0){
        g_lsum[((size_t)ks*BB_ + b)*HW + q0 + qr0] = lr0;
        g_lsum[((size_t)ks*BB_ + b)*HW + q0 + qr1] = lr1;
    }
#pragma unroll
    for (int ct=0; ct<8; ct++){
#pragma unroll
        for (int jj=0; jj<2; jj++){
            int c = ct*8 + 2*tg + jj;
            sOut[c*132 + qr0] = oacc[ct][jj];
            sOut[c*132 + qr1] = oacc[ct][2+jj];
        }
    }
    __syncthreads();
    float* op = g_opart + (size_t)ks*BB_*CI*HW + (size_t)b*CI*HW + q0;
#pragma unroll
    for (int s=0;s<8;s++){
        int idx = tid + s*256; int c = idx>>5, p4 = (idx&31)*4;
        float4 f;
        f.x = sOut[c*132 + p4+0];
        f.y = sOut[c*132 + p4+1];
        f.z = sOut[c*132 + p4+2];
        f.w = sOut[c*132 + p4+3];
        *(float4*)(op + (size_t)c*HW + p4) = f;
    }
}

// ---------------- K4: partial Gram G = fa fa^T, 4 chunks per CTA ----------------
__global__ __launch_bounds__(256) void kGram()
{
    __shared__ float sF[64][68]; // [n][c]
    int b = blockIdx.y;
    int tid=threadIdx.x, ty=tid>>4, tx=tid&15;
    float acc[4][4];
#pragma unroll
    for (int i=0;i<4;i++)
#pragma unroll
        for (int j=0;j<4;j++) acc[i][j]=0.f;

    for (int ch=0; ch<4; ch++){
        int p0 = (blockIdx.x*4 + ch)*64;
        const float* fab = g_fcb + (size_t)b*CI*HW + p0;
        __syncthreads();
#pragma unroll
        for (int s=0;s<4;s++){
            int idx=tid+s*256; int c=idx>>4, nc=(idx&15)*4;
            float4 v = *(const float4*)(fab + (size_t)c*HW + nc);
            sF[nc+0][c]=v.x; sF[nc+1][c]=v.y; sF[nc+2][c]=v.z; sF[nc+3][c]=v.w;
        }
        __syncthreads();
#pragma unroll 4
        for (int n=0;n<64;n++){
            float4 a4 = *(float4*)&sF[n][ty*4];
            float4 b4 = *(float4*)&sF[n][tx*4];
            float a[4]={a4.x,a4.y,a4.z,a4.w}, bv[4]={b4.x,b4.y,b4.z,b4.w};
#pragma unroll
            for (int i=0;i<4;i++)
#pragma unroll
                for (int j=0;j<4;j++)
                    acc[i][j] = fmaf(a[i], bv[j], acc[i][j]);
        }
    }
    float* G = g_gram + b*CI*CI;
#pragma unroll
    for (int i=0;i<4;i++)
#pragma unroll
        for (int j=0;j<4;j++)
            atomicAdd(&G[(ty*4+i)*CI + tx*4+j], acc[i][j]);
}

// ---------------- K5 (fused softC+D+E): channel softmax + fusion + out conv ----------------
// 64-px tiles, grid (64 px, 4 batch), 256 thr
__global__ __launch_bounds__(256) void kDE(
    const float* __restrict__ beta, const float* __restrict__ alpha,
    const float* __restrict__ wo, const float* __restrict__ go, const float* __restrict__ bo,
    const float* __restrict__ mo, const float* __restrict__ vo, float* __restrict__ out)
{
    extern __shared__ float sm[];
    float (*sAt)[68] = (float(*)[68])sm;                // attn^T [d][c]
    float (*sFu)[68] = (float(*)[68])(sm + 64*68);      // fcb -> fusion tile
    float* sRs = sm + 2*64*68;                          // [64]
    float* sW  = sRs + 64;                              // [128][68]; phase0: gram [64][68]
    float (*sG)[68] = (float(*)[68])sW;
    unsigned uW = smem_u32(sW);

    int p0=blockIdx.x*64, b=blockIdx.y;
    int tid=threadIdx.x, lane=tid&31, w=tid>>5;
    int ty=tid>>4, tx=tid&15;
    int wm=w>>1, wn=w&1;

    // ---- phase 0: load gram + fcb + lsum; compute channel softmax into sAt ----
#pragma unroll
    for (int s=0;s<4;s++){
        int idx=tid+s*256; int c=idx>>4, dc=(idx&15)*4;
        *(float4*)&sG[c][dc] = *(const float4*)(g_gram + b*CI*CI + c*CI + dc);
    }
    const float* fab = g_fcb + (size_t)b*CI*HW + p0;
#pragma unroll
    for (int s=0;s<4;s++){
        int idx=tid+s*256; int d=idx>>4, pc=(idx&15)*4;
        *(float4*)&sFu[d][pc] = *(const float4*)(fab + (size_t)d*HW + pc);
    }
    if (tid < 64){
        float l = 0.f;
#pragma unroll
        for (int ksl=0; ksl<NSPLIT; ksl++)
            l += g_lsum[((size_t)ksl*BB_ + b)*HW + p0 + tid];
        sRs[tid] = __ldg(alpha) / l;
    }
    __syncthreads();
    {
        int rc = tid>>2, rq = tid&3;       // 4 threads per gram row
        float e[16];
        float vmin = 1e30f;
#pragma unroll
        for (int j=0;j<16;j++) vmin = fminf(vmin, sG[rc][rq*16+j]);
        vmin = fminf(vmin, __shfl_xor_sync(0xffffffffu, vmin, 1));
        vmin = fminf(vmin, __shfl_xor_sync(0xffffffffu, vmin, 2));
        float sum = 0.f;
#pragma unroll
        for (int j=0;j<16;j++){ e[j] = expf(vmin - sG[rc][rq*16+j]); sum += e[j]; }
        sum += __shfl_xor_sync(0xffffffffu, sum, 1);
        sum += __shfl_xor_sync(0xffffffffu, sum, 2);
        float rs = 1.f/sum;
#pragma unroll
        for (int j=0;j<16;j++) sAt[rq*16+j][rc] = e[j]*rs;
    }
    __syncthreads();

    // ---- phase 1: acc1 = attn @ fcb; fusion into sFu ----
    float acc1[4][4];
#pragma unroll
    for (int i=0;i<4;i++)
#pragma unroll
        for (int j=0;j<4;j++) acc1[i][j]=0.f;
#pragma unroll 4
    for (int d=0;d<64;d++){
        float4 a4 = *(float4*)&sAt[d][ty*4];
        float a[4]={a4.x,a4.y,a4.z,a4.w};
        float4 b4 = *(float4*)&sFu[d][tx*4];
        float bv[4]={b4.x,b4.y,b4.z,b4.w};
#pragma unroll
        for (int i=0;i<4;i++)
#pragma unroll
            for (int j=0;j<4;j++)
                acc1[i][j] = fmaf(a[i], bv[j], acc1[i][j]);
    }
    __syncthreads();
    float bt = __ldg(beta);
    const size_t OSZ = (size_t)BB_*CI*HW;
#pragma unroll
    for (int i=0;i<4;i++){
        int c = ty*4+i;
        int pxb = tx*4;
        size_t off = (size_t)(b*CI+c)*HW + p0 + pxb;
        float4 fp4  = *(const float4*)(g_fp    + off);
        float4 osum = *(const float4*)(g_opart + off);
#pragma unroll
        for (int ksl=1; ksl<NSPLIT; ksl++){
            float4 oo = *(const float4*)(g_opart + (size_t)ksl*OSZ + off);
            osum.x += oo.x; osum.y += oo.y; osum.z += oo.z; osum.w += oo.w;
        }
        float fcx = sFu[c][pxb+0], fcy = sFu[c][pxb+1], fcz = sFu[c][pxb+2], fcw = sFu[c][pxb+3];
        sFu[c][pxb+0] = fp4.x + sRs[pxb+0]*osum.x + bt*acc1[i][0] + fcx;
        sFu[c][pxb+1] = fp4.y + sRs[pxb+1]*osum.y + bt*acc1[i][1] + fcy;
        sFu[c][pxb+2] = fp4.z + sRs[pxb+2]*osum.z + bt*acc1[i][2] + fcz;
        sFu[c][pxb+3] = fp4.w + sRs[pxb+3]*osum.w + bt*acc1[i][3] + fcw;
    }
    __syncthreads();

    // ---- phase 2 (bf16x3 mma): out conv, 4 o-blocks of 128 ----
    int orow = wm*32 + (lane>>2);
    int pxr  = wn*32 + (lane>>2);
    for (int ob=0; ob<4; ob++){
#pragma unroll
        for (int s=0;s<8;s++){
            int idx = tid + s*256;
            int o = idx>>4, kq = (idx&15)*4;
            CPA(uW + (unsigned)((o*68 + kq)*4), wo + (size_t)(ob*128+o)*CI + kq);
        }
        CP_COMMIT(); CP_WAIT(0);
        __syncthreads();

        float acc[2][4][4];
#pragma unroll
        for (int mt=0;mt<2;mt++)
#pragma unroll
            for (int nt=0;nt<4;nt++){ acc[mt][nt][0]=0.f; acc[mt][nt][1]=0.f; acc[mt][nt][2]=0.f; acc[mt][nt][3]=0.f; }

#pragma unroll
        for (int kst=0;kst<4;kst++){
            int kk2 = kst*16 + (lane&3)*2;
            unsigned Ah[2][4], Al[2][4];
#pragma unroll
            for (int mt=0;mt<2;mt++){
                int ro = (orow + mt*16)*68;
                float2 p0v = *(const float2*)&sW[ro + kk2];
                float2 p1v = *(const float2*)&sW[ro + 8*68 + kk2];
                float2 p2v = *(const float2*)&sW[ro + kk2 + 8];
                float2 p3v = *(const float2*)&sW[ro + 8*68 + kk2 + 8];
                split_bf16x2(p0v.x, p0v.y, Ah[mt][0], Al[mt][0]);
                split_bf16x2(p1v.x, p1v.y, Ah[mt][1], Al[mt][1]);
                split_bf16x2(p2v.x, p2v.y, Ah[mt][2], Al[mt][2]);
                split_bf16x2(p3v.x, p3v.y, Ah[mt][3], Al[mt][3]);
            }
            unsigned Bh[4][2], Bl[4][2];
#pragma unroll
            for (int nt=0;nt<4;nt++){
                int col = pxr + nt*8;
                split_bf16x2(sFu[kk2  ][col], sFu[kk2+1][col], Bh[nt][0], Bl[nt][0]);
                split_bf16x2(sFu[kk2+8][col], sFu[kk2+9][col], Bh[nt][1], Bl[nt][1]);
            }
#pragma unroll
            for (int mt=0;mt<2;mt++)
#pragma unroll
                for (int nt=0;nt<4;nt++){
                    mma16816(acc[mt][nt], Al[mt], Bh[nt][0], Bh[nt][1]);
                    mma16816(acc[mt][nt], Ah[mt], Bl[nt][0], Bl[nt][1]);
                    mma16816(acc[mt][nt], Ah[mt], Bh[nt][0], Bh[nt][1]);
                }
        }
#pragma unroll
        for (int mt=0;mt<2;mt++){
#pragma unroll
            for (int sel=0;sel<2;sel++){
                int oc = ob*128 + wm*32 + mt*16 + (lane>>2) + sel*8;
                float inv = go[oc]*rsqrtf(vo[oc]+EPS);
                float bias = bo[oc]-mo[oc]*inv;
                float* dst = out + (size_t)(b*CIN+oc)*HW;
#pragma unroll
                for (int nt=0;nt<4;nt++){
                    float2 v;
                    v.x = acc[mt][nt][sel*2+0]*inv+bias;
                    v.y = acc[mt][nt][sel*2+1]*inv+bias;
                    *(float2*)&dst[p0 + wn*32 + nt*8 + (lane&3)*2] = v;
                }
            }
        }
        __syncthreads();
    }
}

// ---------------- launch ----------------
extern "C" void kernel_launch(void* const* d_in, const int* in_sizes, int n_in,
                              void* d_out, int out_size)
{
    const float* x    = (const float*)d_in[0];
    const float* wp1  = (const float*)d_in[1];
    const float* gp1  = (const float*)d_in[2];
    const float* bp1  = (const float*)d_in[3];
    const float* mp1  = (const float*)d_in[4];
    const float* vp1  = (const float*)d_in[5];
    const float* wc1  = (const float*)d_in[6];
    const float* gc1  = (const float*)d_in[7];
    const float* bc1  = (const float*)d_in[8];
    const float* mc1  = (const float*)d_in[9];
    const float* vc1  = (const float*)d_in[10];
    const float* wb   = (const float*)d_in[11];
    const float* bb   = (const float*)d_in[12];
    const float* wc2  = (const float*)d_in[13];
    const float* bc2  = (const float*)d_in[14];
    const float* wd   = (const float*)d_in[15];
    const float* bd   = (const float*)d_in[16];
    const float* alpha= (const float*)d_in[17];
    const float* beta = (const float*)d_in[18];
    const float* wo   = (const float*)d_in[19];
    const float* go   = (const float*)d_in[20];
    const float* bo   = (const float*)d_in[21];
    const float* mo   = (const float*)d_in[22];
    const float* vo   = (const float*)d_in[23];
    float* out = (float*)d_out;

    const int SMEM_A  = 36864 + 2*8704;                   // 54272
    const int SMEM_B  = (3*64*68 + 64*68) * 4;            // 69632
    const int SMEM_C  = 73728;
    const int SMEM_DE = (2*64*68 + 64 + 128*68) * 4;      // 69888
    cudaFuncSetAttribute(kA,  cudaFuncAttributeMaxDynamicSharedMemorySize, SMEM_A);
    cudaFuncSetAttribute(kB,  cudaFuncAttributeMaxDynamicSharedMemorySize, SMEM_B);
    cudaFuncSetAttribute(kCm, cudaFuncAttributeMaxDynamicSharedMemorySize, SMEM_C);
    cudaFuncSetAttribute(kDE, cudaFuncAttributeMaxDynamicSharedMemorySize, SMEM_DE);

    kA<<<dim3(64,4),256,SMEM_A>>>(x, wp1,gp1,bp1,mp1,vp1, wc1,gc1,bc1,mc1,vc1);
    kB<<<dim3(64,4),256,SMEM_B>>>(wb,bb,wc2,bc2,wd,bd);
    kCm<<<dim3(32,NSPLIT,4),256,SMEM_C>>>();
    kGram<<<dim3(16,4),256>>>();
    kDE<<<dim3(64,4),256,SMEM_DE>>>(beta, alpha, wo,go,bo,mo,vo,out);
}

// round 16
// speedup vs baseline: 1.2386x; 1.0105x over previous
#include <cuda_runtime.h>
#include <cuda_bf16.h>
#include <math.h>

#define EPS 1e-5f
#define BB_ 4
#define CIN 512
#define CI 64
#define HW 4096
#define NSPLIT 4
#define LOG2E 1.4426950408889634f

// ---------------- scratch (device globals, no allocation) ----------------
__device__ float g_fp[BB_*CI*HW];
__device__ float g_fcb[BB_*CI*HW];
__device__ float g_gram[BB_*CI*CI];
__device__ float g_opart[NSPLIT*BB_*CI*HW];  // partial attention O
__device__ float g_lsum[NSPLIT*BB_*HW];      // partial softmax denominators
// bf16 tensors for mma attention, all pixel-major [b][px][c]
__device__ __nv_bfloat16 g_fbt[BB_*HW*CI];   // Q (pre-scaled by log2e)
__device__ __nv_bfloat16 g_fct[BB_*HW*CI];   // K
__device__ __nv_bfloat16 g_fdt[BB_*HW*CI];   // V

// ================= PTX helpers (baseline ISA only, sm_80+) =================
static __device__ __forceinline__ unsigned smem_u32(const void* p){
    unsigned a; asm("{ .reg .u64 t; cvta.to.shared.u64 t, %1; cvt.u32.u64 %0, t; }":"=r"(a):"l"(p)); return a;
}
static __device__ __forceinline__ unsigned pack_bf16x2(float lo, float hi){
    unsigned r; asm("cvt.rn.bf16x2.f32 %0, %1, %2;" : "=r"(r) : "f"(hi), "f"(lo)); return r;
}
static __device__ __forceinline__ float ex2f(float x){
    float r; asm("ex2.approx.f32 %0, %1;" : "=f"(r) : "f"(x)); return r;
}
static __device__ __forceinline__ void ldsm4(unsigned* r, unsigned addr){
    asm volatile("ldmatrix.sync.aligned.m8n8.x4.shared.b16 {%0,%1,%2,%3}, [%4];"
        : "=r"(r[0]),"=r"(r[1]),"=r"(r[2]),"=r"(r[3]) : "r"(addr));
}
static __device__ __forceinline__ void ldsm4t(unsigned* r, unsigned addr){
    asm volatile("ldmatrix.sync.aligned.m8n8.x4.trans.shared.b16 {%0,%1,%2,%3}, [%4];"
        : "=r"(r[0]),"=r"(r[1]),"=r"(r[2]),"=r"(r[3]) : "r"(addr));
}
static __device__ __forceinline__ void mma16816(float* d, const unsigned* a, unsigned b0, unsigned b1){
    asm volatile("mma.sync.aligned.m16n8k16.row.col.f32.bf16.bf16.f32 "
        "{%0,%1,%2,%3}, {%4,%5,%6,%7}, {%8,%9}, {%0,%1,%2,%3};"
        : "+f"(d[0]),"+f"(d[1]),"+f"(d[2]),"+f"(d[3])
        : "r"(a[0]),"r"(a[1]),"r"(a[2]),"r"(a[3]), "r"(b0),"r"(b1));
}
// split-precision bf16: v = hi + lo, hi = truncate-to-bf16(v)
static __device__ __forceinline__ void split_bf16x2(float v0, float v1, unsigned& hi, unsigned& lo){
    unsigned u0 = __float_as_uint(v0), u1 = __float_as_uint(v1);
    asm("prmt.b32 %0, %1, %2, 0x7632;" : "=r"(hi) : "r"(u0), "r"(u1));
    float l0 = v0 - __uint_as_float(u0 & 0xFFFF0000u);
    float l1 = v1 - __uint_as_float(u1 & 0xFFFF0000u);
    lo = pack_bf16x2(l0, l1);
}
#define CPA(dst, src) asm volatile("cp.async.ca.shared.global [%0], [%1], 16;" :: "r"(dst), "l"(src))
#define CP_COMMIT()   asm volatile("cp.async.commit_group;" ::: "memory")
#define CP_WAIT(n)    asm volatile("cp.async.wait_group %0;" :: "n"(n) : "memory")

// ---------------- K1 (bf16x3 mma): x(512) -> fp(64), fcb(64), BN fold ----------------
__global__ __launch_bounds__(256) void kA(
    const float* __restrict__ x,
    const float* __restrict__ wp1, const float* __restrict__ gp1, const float* __restrict__ bp1,
    const float* __restrict__ mp1, const float* __restrict__ vp1,
    const float* __restrict__ wc1, const float* __restrict__ gc1, const float* __restrict__ bc1,
    const float* __restrict__ mc1, const float* __restrict__ vc1)
{
    extern __shared__ char smraw[];
    float* sWf[2] = {(float*)smraw, (float*)(smraw+18432)};
    float* sXf[2] = {(float*)(smraw+36864), (float*)(smraw+36864+8704)};
    unsigned ub = smem_u32(smraw);
    unsigned uW[2] = {ub, ub+18432};
    unsigned uX[2] = {ub+36864, ub+36864+8704};

    int b = blockIdx.y, p0 = blockIdx.x*64;
    int tid=threadIdx.x, lane=tid&31, w=tid>>5;
    int wm=w>>1, wn=w&1;
    const float* xb = x + (size_t)b*CIN*HW + p0;

    const float* wsrc[4]; unsigned wdst[4];
    const float* xsrc[2]; unsigned xdst[2]; int xk[2];
#pragma unroll
    for (int s=0;s<4;s++){
        int idx = tid + s*256;
        int o = idx>>3, kq = (idx&7)*4;
        wsrc[s] = (o<64 ? wp1 + (size_t)o*CIN : wc1 + (size_t)(o-64)*CIN) + kq;
        wdst[s] = (unsigned)((o*36 + kq)*4);
    }
#pragma unroll
    for (int s=0;s<2;s++){
        int idx = tid + s*256;
        int k = idx>>4, pq = (idx&15)*4;
        xk[s] = k;
        xsrc[s] = xb + pq;
        xdst[s] = (unsigned)((k*68 + pq)*4);
    }
#pragma unroll
    for (int s=0;s<4;s++) CPA(uW[0]+wdst[s], wsrc[s]);
#pragma unroll
    for (int s=0;s<2;s++) CPA(uX[0]+xdst[s], xsrc[s] + (size_t)xk[s]*HW);
    CP_COMMIT();

    float acc[2][4][4];
#pragma unroll
    for (int mt=0;mt<2;mt++)
#pragma unroll
        for (int nt=0;nt<4;nt++){ acc[mt][nt][0]=0.f; acc[mt][nt][1]=0.f; acc[mt][nt][2]=0.f; acc[mt][nt][3]=0.f; }

    int orow = wm*32 + (lane>>2);
    int pxr  = wn*32 + (lane>>2);

    for (int c=0;c<16;c++){
        if (c<15){
            int k0 = (c+1)*32; int nb=(c+1)&1;
#pragma unroll
            for (int s=0;s<4;s++) CPA(uW[nb]+wdst[s], wsrc[s]+k0);
#pragma unroll
            for (int s=0;s<2;s++) CPA(uX[nb]+xdst[s], xsrc[s] + (size_t)(k0+xk[s])*HW);
            CP_COMMIT(); CP_WAIT(1);
        } else { CP_WAIT(0); }
        __syncthreads();
        const float* Wb = sWf[c&1]; const float* Xb = sXf[c&1];
#pragma unroll
        for (int kst=0;kst<2;kst++){
            int kk2 = kst*16 + (lane&3)*2;
            unsigned Ah[2][4], Al[2][4];
#pragma unroll
            for (int mt=0;mt<2;mt++){
                int ro = (orow + mt*16)*36;
                float2 p0 = *(const float2*)&Wb[ro + kk2];
                float2 p1 = *(const float2*)&Wb[ro + 8*36 + kk2];
                float2 p2 = *(const float2*)&Wb[ro + kk2 + 8];
                float2 p3 = *(const float2*)&Wb[ro + 8*36 + kk2 + 8];
                split_bf16x2(p0.x, p0.y, Ah[mt][0], Al[mt][0]);
                split_bf16x2(p1.x, p1.y, Ah[mt][1], Al[mt][1]);
                split_bf16x2(p2.x, p2.y, Ah[mt][2], Al[mt][2]);
                split_bf16x2(p3.x, p3.y, Ah[mt][3], Al[mt][3]);
            }
            unsigned Bh[4][2], Bl[4][2];
#pragma unroll
            for (int nt=0;nt<4;nt++){
                int col = pxr + nt*8;
                split_bf16x2(Xb[(kk2  )*68 + col], Xb[(kk2+1)*68 + col], Bh[nt][0], Bl[nt][0]);
                split_bf16x2(Xb[(kk2+8)*68 + col], Xb[(kk2+9)*68 + col], Bh[nt][1], Bl[nt][1]);
            }
#pragma unroll
            for (int mt=0;mt<2;mt++)
#pragma unroll
                for (int nt=0;nt<4;nt++){
                    mma16816(acc[mt][nt], Al[mt], Bh[nt][0], Bh[nt][1]);
                    mma16816(acc[mt][nt], Ah[mt], Bl[nt][0], Bl[nt][1]);
                    mma16816(acc[mt][nt], Ah[mt], Bh[nt][0], Bh[nt][1]);
                }
        }
        __syncthreads();
    }
#pragma unroll
    for (int mt=0;mt<2;mt++){
#pragma unroll
        for (int sel=0;sel<2;sel++){
            int oc = wm*32 + mt*16 + (lane>>2) + sel*8;
            float inv, bias; float* dst;
            if (oc<64){ inv=gp1[oc]*rsqrtf(vp1[oc]+EPS); bias=bp1[oc]-mp1[oc]*inv;
                        dst=g_fp+(size_t)(b*CI+oc)*HW; }
            else      { int o2=oc-64; inv=gc1[o2]*rsqrtf(vc1[o2]+EPS); bias=bc1[o2]-mc1[o2]*inv;
                        dst=g_fcb+(size_t)(b*CI+o2)*HW; }
#pragma unroll
            for (int nt=0;nt<4;nt++){
                float2 v;
                v.x = acc[mt][nt][sel*2+0]*inv+bias;
                v.y = acc[mt][nt][sel*2+1]*inv+bias;
                *(float2*)&dst[p0 + wn*32 + nt*8 + (lane&3)*2] = v;
            }
        }
    }
}

// ---------------- K2: fp(64) -> Q/K/V pixel-major bf16; also zeroes g_gram ----------------
__global__ __launch_bounds__(256) void kB(
    const float* __restrict__ wb,  const float* __restrict__ bb,
    const float* __restrict__ wc2, const float* __restrict__ bc2,
    const float* __restrict__ wd,  const float* __restrict__ bd)
{
    extern __shared__ float sm[];
    float* sW3 = sm;                                   // [3][64][68]
    float (*sF)[68] = (float(*)[68])(sm + 3*64*68);    // [k][p]
    int p0 = blockIdx.x*64, b = blockIdx.y;
    int tid=threadIdx.x, ty=tid>>4, tx=tid&15;

    if (tid < 64) g_gram[(blockIdx.y*64 + blockIdx.x)*64 + tid] = 0.f;

    const float* Ws[3] = {wb, wc2, wd};
#pragma unroll
    for (int sel=0;sel<3;sel++){
        float fac = (sel==0) ? LOG2E : 1.f;
        float* sW = sW3 + sel*64*68;
#pragma unroll
        for (int s=0;s<4;s++){
            int idx = tid + s*256;
            int j = idx>>4, cc = (idx&15)*4;
            float4 v = *(const float4*)(Ws[sel] + j*64 + cc);
            sW[(cc+0)*68+j]=v.x*fac; sW[(cc+1)*68+j]=v.y*fac; sW[(cc+2)*68+j]=v.z*fac; sW[(cc+3)*68+j]=v.w*fac;
        }
    }
    const float* fpb = g_fp + (size_t)b*CI*HW + p0;
#pragma unroll
    for (int s=0;s<4;s++){
        int idx = tid + s*256;
        int k = idx>>4, pc = (idx&15)*4;
        *(float4*)&sF[k][pc] = *(const float4*)(fpb + (size_t)k*HW + pc);
    }
    __syncthreads();
    const float* biasArr[3] = {bb, bc2, bd};
    __nv_bfloat16* dsts[3] = {g_fbt, g_fct, g_fdt};
#pragma unroll
    for (int sel=0;sel<3;sel++){
        float fac = (sel==0) ? LOG2E : 1.f;
        const float* sW = sW3 + sel*64*68;
        const float* bias = biasArr[sel];
        float acc[4][4];
#pragma unroll
        for (int i=0;i<4;i++)
#pragma unroll
            for (int j=0;j<4;j++) acc[i][j]=0.f;
        for (int k=0;k<64;k++){
            float a[4], bv[4];
#pragma unroll
            for (int i=0;i<4;i++) a[i]=sW[k*68 + ty*4+i];
#pragma unroll
            for (int j=0;j<4;j++) bv[j]=sF[k][tx*4+j];
#pragma unroll
            for (int i=0;i<4;i++)
#pragma unroll
                for (int j=0;j<4;j++)
                    acc[i][j] = fmaf(a[i], bv[j], acc[i][j]);
        }
        __nv_bfloat16* dstT = dsts[sel] + ((size_t)b*HW + p0)*CI;
        float bi0=bias[ty*4+0]*fac, bi1=bias[ty*4+1]*fac, bi2=bias[ty*4+2]*fac, bi3=bias[ty*4+3]*fac;
#pragma unroll
        for (int j=0;j<4;j++){
            uint2 v;
            v.x = pack_bf16x2(acc[0][j]+bi0, acc[1][j]+bi1);
            v.y = pack_bf16x2(acc[2][j]+bi2, acc[3][j]+bi3);
            *(uint2*)((char*)dstT + ((size_t)(tx*4+j)*CI + ty*4)*2) = v;
        }
    }
}

// ---------------- K3: mma.sync flash attention, k-split x4, cp.async double-buffered ----------------
#define QSTR 144   // bytes per smem row (72 bf16)
__global__ __launch_bounds__(256) void kCm()
{
    extern __shared__ char smem[];
    const int SKb0=0, SKb1=18432, SVb0=36864, SVb1=55296;
    float* sOut = (float*)smem;
    unsigned sb = smem_u32(smem);
    int tid=threadIdx.x, lane=tid&31, w=tid>>5;
    int b=blockIdx.z, ks=blockIdx.y, q0=blockIdx.x*128;
    int g = lane>>2, tg = lane&3;
    const int NT = 32/NSPLIT;
    const int T0 = ks*NT;

    const char* Qg = (const char*)(g_fbt + ((size_t)b*HW + q0)*CI);
    const char* Kg = (const char*)(g_fct + (size_t)b*HW*CI);
    const char* Vg = (const char*)(g_fdt + (size_t)b*HW*CI);

    int pxl[4], chl[4];
#pragma unroll
    for (int s=0;s<4;s++){ int idx = tid + s*256; pxl[s]=idx>>3; chl[s]=(idx&7)*8; }

#pragma unroll
    for (int s=0;s<4;s++){
        unsigned so = (unsigned)(pxl[s]*QSTR + chl[s]*2);
        size_t  go = ((size_t)pxl[s]*CI + chl[s])*2;
        size_t  gk = (((size_t)T0*128 + pxl[s])*CI + chl[s])*2;
        CPA(sb+SKb1+so, Qg + go);
        CPA(sb+SKb0+so, Kg + gk);
        CPA(sb+SVb0+so, Vg + gk);
    }
    CP_COMMIT(); CP_WAIT(0);
    __syncthreads();

    unsigned aQ[4][4];
    {
        unsigned rb = sb + SKb1 + (unsigned)((16*w + (lane&15))*QSTR) + (unsigned)((lane>>4)*16);
#pragma unroll
        for (int kq=0; kq<4; kq++) ldsm4(aQ[kq], rb + kq*32);
    }
    __syncthreads();

    float oacc[8][4];
#pragma unroll
    for (int i=0;i<8;i++){ oacc[i][0]=0.f; oacc[i][1]=0.f; oacc[i][2]=0.f; oacc[i][3]=0.f; }
    float lr0 = 0.f, lr1 = 0.f;

    for (int tt=0; tt<NT; tt++){
        if (tt<NT-1){
            unsigned SKn = ((tt+1)&1)? SKb1 : SKb0;
            unsigned SVn = ((tt+1)&1)? SVb1 : SVb0;
            size_t kn = (size_t)(T0+tt+1)*128;
#pragma unroll
            for (int s=0;s<4;s++){
                unsigned so = (unsigned)(pxl[s]*QSTR + chl[s]*2);
                size_t  go = ((kn + pxl[s])*CI + chl[s])*2;
                CPA(sb+SKn+so, Kg + go);
                CPA(sb+SVn+so, Vg + go);
            }
            CP_COMMIT(); CP_WAIT(1);
        } else { CP_WAIT(0); }
        __syncthreads();

        unsigned SKc = (tt&1)? SKb1 : SKb0;
        unsigned SVc = (tt&1)? SVb1 : SVb0;

        float sacc[16][4];
#pragma unroll
        for (int nt=0; nt<16; nt++){ sacc[nt][0]=0.f; sacc[nt][1]=0.f; sacc[nt][2]=0.f; sacc[nt][3]=0.f; }
#pragma unroll
        for (int nt=0; nt<16; nt++){
            unsigned addr = sb + SKc + (unsigned)((nt*8 + (lane&7))*QSTR) + (unsigned)((lane>>3)*16);
            unsigned b0[4], b1[4];
            ldsm4(b0, addr);
            ldsm4(b1, addr + 64);
            mma16816(sacc[nt], aQ[0], b0[0], b0[1]);
            mma16816(sacc[nt], aQ[1], b0[2], b0[3]);
            mma16816(sacc[nt], aQ[2], b1[0], b1[1]);
            mma16816(sacc[nt], aQ[3], b1[2], b1[3]);
        }

        unsigned aP[8][4];
#pragma unroll
        for (int nt=0; nt<16; nt++){
            float e0 = ex2f(sacc[nt][0]);
            float e1 = ex2f(sacc[nt][1]);
            float e2 = ex2f(sacc[nt][2]);
            float e3 = ex2f(sacc[nt][3]);
            lr0 += e0 + e1; lr1 += e2 + e3;
            sacc[nt][0]=e0; sacc[nt][1]=e1; sacc[nt][2]=e2; sacc[nt][3]=e3;
        }
#pragma unroll
        for (int s2=0; s2<8; s2++){
            aP[s2][0] = pack_bf16x2(sacc[2*s2  ][0], sacc[2*s2  ][1]);
            aP[s2][1] = pack_bf16x2(sacc[2*s2  ][2], sacc[2*s2  ][3]);
            aP[s2][2] = pack_bf16x2(sacc[2*s2+1][0], sacc[2*s2+1][1]);
            aP[s2][3] = pack_bf16x2(sacc[2*s2+1][2], sacc[2*s2+1][3]);
        }

#pragma unroll
        for (int s2=0; s2<8; s2++){
            unsigned rowa = (unsigned)((s2*16 + (lane&7) + ((lane>>3)&1)*8)*QSTR);
#pragma unroll
            for (int cp=0; cp<4; cp++){
                unsigned addr = sb + SVc + rowa + (unsigned)(cp*32 + (lane>>4)*16);
                unsigned bv[4];
                ldsm4t(bv, addr);
                mma16816(oacc[2*cp  ], aP[s2], bv[0], bv[1]);
                mma16816(oacc[2*cp+1], aP[s2], bv[2], bv[3]);
            }
        }
        __syncthreads();
    }

#pragma unroll
    for (int off=1; off<4; off<<=1){
        lr0 += __shfl_xor_sync(0xffffffffu, lr0, off);
        lr1 += __shfl_xor_sync(0xffffffffu, lr1, off);
    }
    int qr0 = 16*w + g, qr1 = qr0 + 8;
    if (tg==0){
        g_lsum[((size_t)ks*BB_ + b)*HW + q0 + qr0] = lr0;
        g_lsum[((size_t)ks*BB_ + b)*HW + q0 + qr1] = lr1;
    }
#pragma unroll
    for (int ct=0; ct<8; ct++){
#pragma unroll
        for (int jj=0; jj<2; jj++){
            int c = ct*8 + 2*tg + jj;
            sOut[c*132 + qr0] = oacc[ct][jj];
            sOut[c*132 + qr1] = oacc[ct][2+jj];
        }
    }
    __syncthreads();
    float* op = g_opart + (size_t)ks*BB_*CI*HW + (size_t)b*CI*HW + q0;
#pragma unroll
    for (int s=0;s<8;s++){
        int idx = tid + s*256; int c = idx>>5, p4 = (idx&31)*4;
        float4 f;
        f.x = sOut[c*132 + p4+0];
        f.y = sOut[c*132 + p4+1];
        f.z = sOut[c*132 + p4+2];
        f.w = sOut[c*132 + p4+3];
        *(float4*)(op + (size_t)c*HW + p4) = f;
    }
}

// ---------------- K4: partial Gram G = fa fa^T, 64-px chunk per CTA ----------------
// grid (64, 4) = 256 CTAs
__global__ __launch_bounds__(256) void kGram()
{
    __shared__ float sF[64][68]; // [n][c]
    int p0 = blockIdx.x*64, b = blockIdx.y;
    const float* fab = g_fcb + (size_t)b*CI*HW + p0;
    int tid=threadIdx.x, ty=tid>>4, tx=tid&15;
#pragma unroll
    for (int s=0;s<4;s++){
        int idx=tid+s*256; int c=idx>>4, nc=(idx&15)*4;
        float4 v = *(const float4*)(fab + (size_t)c*HW + nc);
        sF[nc+0][c]=v.x; sF[nc+1][c]=v.y; sF[nc+2][c]=v.z; sF[nc+3][c]=v.w;
    }
    __syncthreads();
    float acc[4][4];
#pragma unroll
    for (int i=0;i<4;i++)
#pragma unroll
        for (int j=0;j<4;j++) acc[i][j]=0.f;
#pragma unroll 4
    for (int n=0;n<64;n++){
        float4 a4 = *(float4*)&sF[n][ty*4];
        float4 b4 = *(float4*)&sF[n][tx*4];
        float a[4]={a4.x,a4.y,a4.z,a4.w}, bv[4]={b4.x,b4.y,b4.z,b4.w};
#pragma unroll
        for (int i=0;i<4;i++)
#pragma unroll
            for (int j=0;j<4;j++)
                acc[i][j] = fmaf(a[i], bv[j], acc[i][j]);
    }
    float* G = g_gram + b*CI*CI;
#pragma unroll
    for (int i=0;i<4;i++)
#pragma unroll
        for (int j=0;j<4;j++)
            atomicAdd(&G[(ty*4+i)*CI + tx*4+j], acc[i][j]);
}

// ---------------- K5 (fused softC+D+E): channel softmax + fusion + out conv ----------------
// 64-px tiles, grid (64 px, 4 batch), 256 thr, double-buffered weights
__global__ __launch_bounds__(256) void kDE(
    const float* __restrict__ beta, const float* __restrict__ alpha,
    const float* __restrict__ wo, const float* __restrict__ go, const float* __restrict__ bo,
    const float* __restrict__ mo, const float* __restrict__ vo, float* __restrict__ out)
{
    extern __shared__ float sm[];
    float (*sAt)[68] = (float(*)[68])sm;                // attn^T [d][c]  17408 B
    float (*sFu)[68] = (float(*)[68])(sm + 64*68);      // fcb -> fusion tile 17408 B
    float* sRs = sm + 2*64*68;                          // [64] (256 B)
    float* sWb[2] = { sm + 2*64*68 + 64, sm + 2*64*68 + 64 + 128*68 };  // 34816 B each
    float (*sG)[68] = (float(*)[68])sWb[1];             // gram staged in buf1 pre-prefetch
    unsigned uWb[2] = { smem_u32(sWb[0]), smem_u32(sWb[1]) };

    int p0=blockIdx.x*64, b=blockIdx.y;
    int tid=threadIdx.x, lane=tid&31, w=tid>>5;
    int ty=tid>>4, tx=tid&15;
    int wm=w>>1, wn=w&1;

    // issue ob=0 weights into buf0 immediately (group 0)
#pragma unroll
    for (int s=0;s<8;s++){
        int idx = tid + s*256;
        int o = idx>>4, kq = (idx&15)*4;
        CPA(uWb[0] + (unsigned)((o*68 + kq)*4), wo + (size_t)o*CI + kq);
    }
    CP_COMMIT();

    // ---- phase 0: gram (into buf1 space) + fcb + lsum; channel softmax -> sAt ----
#pragma unroll
    for (int s=0;s<4;s++){
        int idx=tid+s*256; int c=idx>>4, dc=(idx&15)*4;
        *(float4*)&sG[c][dc] = *(const float4*)(g_gram + b*CI*CI + c*CI + dc);
    }
    const float* fab = g_fcb + (size_t)b*CI*HW + p0;
#pragma unroll
    for (int s=0;s<4;s++){
        int idx=tid+s*256; int d=idx>>4, pc=(idx&15)*4;
        *(float4*)&sFu[d][pc] = *(const float4*)(fab + (size_t)d*HW + pc);
    }
    if (tid < 64){
        float l = 0.f;
#pragma unroll
        for (int ksl=0; ksl<NSPLIT; ksl++)
            l += g_lsum[((size_t)ksl*BB_ + b)*HW + p0 + tid];
        sRs[tid] = __ldg(alpha) / l;
    }
    __syncthreads();
    {
        int rc = tid>>2, rq = tid&3;
        float e[16];
        float vmin = 1e30f;
#pragma unroll
        for (int j=0;j<16;j++) vmin = fminf(vmin, sG[rc][rq*16+j]);
        vmin = fminf(vmin, __shfl_xor_sync(0xffffffffu, vmin, 1));
        vmin = fminf(vmin, __shfl_xor_sync(0xffffffffu, vmin, 2));
        float sum = 0.f;
#pragma unroll
        for (int j=0;j<16;j++){ e[j] = expf(vmin - sG[rc][rq*16+j]); sum += e[j]; }
        sum += __shfl_xor_sync(0xffffffffu, sum, 1);
        sum += __shfl_xor_sync(0xffffffffu, sum, 2);
        float rs = 1.f/sum;
#pragma unroll
        for (int j=0;j<16;j++) sAt[rq*16+j][rc] = e[j]*rs;
    }
    __syncthreads();   // gram fully consumed; buf1 free for ob=1 weights

    // issue ob=1 weights into buf1 (group 1)
#pragma unroll
    for (int s=0;s<8;s++){
        int idx = tid + s*256;
        int o = idx>>4, kq = (idx&15)*4;
        CPA(uWb[1] + (unsigned)((o*68 + kq)*4), wo + (size_t)(128+o)*CI + kq);
    }
    CP_COMMIT();

    // ---- phase 1: acc1 = attn @ fcb; fusion into sFu ----
    float acc1[4][4];
#pragma unroll
    for (int i=0;i<4;i++)
#pragma unroll
        for (int j=0;j<4;j++) acc1[i][j]=0.f;
#pragma unroll 4
    for (int d=0;d<64;d++){
        float4 a4 = *(float4*)&sAt[d][ty*4];
        float a[4]={a4.x,a4.y,a4.z,a4.w};
        float4 b4 = *(float4*)&sFu[d][tx*4];
        float bv[4]={b4.x,b4.y,b4.z,b4.w};
#pragma unroll
        for (int i=0;i<4;i++)
#pragma unroll
            for (int j=0;j<4;j++)
                acc1[i][j] = fmaf(a[i], bv[j], acc1[i][j]);
    }
    __syncthreads();
    float bt = __ldg(beta);
    const size_t OSZ = (size_t)BB_*CI*HW;
#pragma unroll
    for (int i=0;i<4;i++){
        int c = ty*4+i;
        int pxb = tx*4;
        size_t off = (size_t)(b*CI+c)*HW + p0 + pxb;
        float4 fp4  = *(const float4*)(g_fp    + off);
        float4 osum = *(const float4*)(g_opart + off);
#pragma unroll
        for (int ksl=1; ksl<NSPLIT; ksl++){
            float4 oo = *(const float4*)(g_opart + (size_t)ksl*OSZ + off);
            osum.x += oo.x; osum.y += oo.y; osum.z += oo.z; osum.w += oo.w;
        }
        float fcx = sFu[c][pxb+0], fcy = sFu[c][pxb+1], fcz = sFu[c][pxb+2], fcw = sFu[c][pxb+3];
        sFu[c][pxb+0] = fp4.x + sRs[pxb+0]*osum.x + bt*acc1[i][0] + fcx;
        sFu[c][pxb+1] = fp4.y + sRs[pxb+1]*osum.y + bt*acc1[i][1] + fcy;
        sFu[c][pxb+2] = fp4.z + sRs[pxb+2]*osum.z + bt*acc1[i][2] + fcz;
        sFu[c][pxb+3] = fp4.w + sRs[pxb+3]*osum.w + bt*acc1[i][3] + fcw;
    }

    // ---- phase 2 (bf16x3 mma): out conv, 4 o-blocks, double-buffered weights ----
    int orow = wm*32 + (lane>>2);
    int pxr  = wn*32 + (lane>>2);
    for (int ob=0; ob<4; ob++){
        if (ob<3){ CP_WAIT(1); } else { CP_WAIT(0); }
        __syncthreads();   // also covers sFu fusion writes for ob=0
        const float* sW = sWb[ob&1];

        float acc[2][4][4];
#pragma unroll
        for (int mt=0;mt<2;mt++)
#pragma unroll
            for (int nt=0;nt<4;nt++){ acc[mt][nt][0]=0.f; acc[mt][nt][1]=0.f; acc[mt][nt][2]=0.f; acc[mt][nt][3]=0.f; }

#pragma unroll
        for (int kst=0;kst<4;kst++){
            int kk2 = kst*16 + (lane&3)*2;
            unsigned Ah[2][4], Al[2][4];
#pragma unroll
            for (int mt=0;mt<2;mt++){
                int ro = (orow + mt*16)*68;
                float2 p0v = *(const float2*)&sW[ro + kk2];
                float2 p1v = *(const float2*)&sW[ro + 8*68 + kk2];
                float2 p2v = *(const float2*)&sW[ro + kk2 + 8];
                float2 p3v = *(const float2*)&sW[ro + 8*68 + kk2 + 8];
                split_bf16x2(p0v.x, p0v.y, Ah[mt][0], Al[mt][0]);
                split_bf16x2(p1v.x, p1v.y, Ah[mt][1], Al[mt][1]);
                split_bf16x2(p2v.x, p2v.y, Ah[mt][2], Al[mt][2]);
                split_bf16x2(p3v.x, p3v.y, Ah[mt][3], Al[mt][3]);
            }
            unsigned Bh[4][2], Bl[4][2];
#pragma unroll
            for (int nt=0;nt<4;nt++){
                int col = pxr + nt*8;
                split_bf16x2(sFu[kk2  ][col], sFu[kk2+1][col], Bh[nt][0], Bl[nt][0]);
                split_bf16x2(sFu[kk2+8][col], sFu[kk2+9][col], Bh[nt][1], Bl[nt][1]);
            }
#pragma unroll
            for (int mt=0;mt<2;mt++)
#pragma unroll
                for (int nt=0;nt<4;nt++){
                    mma16816(acc[mt][nt], Al[mt], Bh[nt][0], Bh[nt][1]);
                    mma16816(acc[mt][nt], Ah[mt], Bl[nt][0], Bl[nt][1]);
                    mma16816(acc[mt][nt], Ah[mt], Bh[nt][0], Bh[nt][1]);
                }
        }
        __syncthreads();  // done reading sW buf before refilling it
        if (ob+2 <= 3){
#pragma unroll
            for (int s=0;s<8;s++){
                int idx = tid + s*256;
                int o = idx>>4, kq = (idx&15)*4;
                CPA(uWb[ob&1] + (unsigned)((o*68 + kq)*4), wo + (size_t)((ob+2)*128+o)*CI + kq);
            }
            CP_COMMIT();
        }
#pragma unroll
        for (int mt=0;mt<2;mt++){
#pragma unroll
            for (int sel=0;sel<2;sel++){
                int oc = ob*128 + wm*32 + mt*16 + (lane>>2) + sel*8;
                float inv = go[oc]*rsqrtf(vo[oc]+EPS);
                float bias = bo[oc]-mo[oc]*inv;
                float* dst = out + (size_t)(b*CIN+oc)*HW;
#pragma unroll
                for (int nt=0;nt<4;nt++){
                    float2 v;
                    v.x = acc[mt][nt][sel*2+0]*inv+bias;
                    v.y = acc[mt][nt][sel*2+1]*inv+bias;
                    *(float2*)&dst[p0 + wn*32 + nt*8 + (lane&3)*2] = v;
                }
            }
        }
    }
}

// ---------------- launch ----------------
extern "C" void kernel_launch(void* const* d_in, const int* in_sizes, int n_in,
                              void* d_out, int out_size)
{
    const float* x    = (const float*)d_in[0];
    const float* wp1  = (const float*)d_in[1];
    const float* gp1  = (const float*)d_in[2];
    const float* bp1  = (const float*)d_in[3];
    const float* mp1  = (const float*)d_in[4];
    const float* vp1  = (const float*)d_in[5];
    const float* wc1  = (const float*)d_in[6];
    const float* gc1  = (const float*)d_in[7];
    const float* bc1  = (const float*)d_in[8];
    const float* mc1  = (const float*)d_in[9];
    const float* vc1  = (const float*)d_in[10];
    const float* wb   = (const float*)d_in[11];
    const float* bb   = (const float*)d_in[12];
    const float* wc2  = (const float*)d_in[13];
    const float* bc2  = (const float*)d_in[14];
    const float* wd   = (const float*)d_in[15];
    const float* bd   = (const float*)d_in[16];
    const float* alpha= (const float*)d_in[17];
    const float* beta = (const float*)d_in[18];
    const float* wo   = (const float*)d_in[19];
    const float* go   = (const float*)d_in[20];
    const float* bo   = (const float*)d_in[21];
    const float* mo   = (const float*)d_in[22];
    const float* vo   = (const float*)d_in[23];
    float* out = (float*)d_out;

    const int SMEM_A  = 36864 + 2*8704;                      // 54272
    const int SMEM_B  = (3*64*68 + 64*68) * 4;               // 69632
    const int SMEM_C  = 73728;
    const int SMEM_DE = (2*64*68 + 64 + 2*128*68) * 4;       // 104704
    cudaFuncSetAttribute(kA,  cudaFuncAttributeMaxDynamicSharedMemorySize, SMEM_A);
    cudaFuncSetAttribute(kB,  cudaFuncAttributeMaxDynamicSharedMemorySize, SMEM_B);
    cudaFuncSetAttribute(kCm, cudaFuncAttributeMaxDynamicSharedMemorySize, SMEM_C);
    cudaFuncSetAttribute(kDE, cudaFuncAttributeMaxDynamicSharedMemorySize, SMEM_DE);

    kA<<<dim3(64,4),256,SMEM_A>>>(x, wp1,gp1,bp1,mp1,vp1, wc1,gc1,bc1,mc1,vc1);
    kB<<<dim3(64,4),256,SMEM_B>>>(wb,bb,wc2,bc2,wd,bd);
    kCm<<<dim3(32,NSPLIT,4),256,SMEM_C>>>();
    kGram<<<dim3(64,4),256>>>();
    kDE<<<dim3(64,4),256,SMEM_DE>>>(beta, alpha, wo,go,bo,mo,vo,out);
}

// round 17
// speedup vs baseline: 1.2468x; 1.0066x over previous
#include <cuda_runtime.h>
#include <cuda_bf16.h>
#include <math.h>

#define EPS 1e-5f
#define BB_ 4
#define CIN 512
#define CI 64
#define HW 4096
#define NSPLIT 4
#define LOG2E 1.4426950408889634f

// ---------------- scratch (device globals, no allocation) ----------------
__device__ float g_fp[BB_*CI*HW];
__device__ float g_fcb[BB_*CI*HW];
__device__ float g_gram[BB_*CI*CI];
__device__ float g_opart[NSPLIT*BB_*CI*HW];  // partial attention O
__device__ float g_lsum[NSPLIT*BB_*HW];      // partial softmax denominators
// bf16 tensors for mma attention, all pixel-major [b][px][c]
__device__ __nv_bfloat16 g_fbt[BB_*HW*CI];   // Q (pre-scaled by log2e)
__device__ __nv_bfloat16 g_fct[BB_*HW*CI];   // K
__device__ __nv_bfloat16 g_fdt[BB_*HW*CI];   // V

// ================= PTX helpers (baseline ISA only, sm_80+) =================
static __device__ __forceinline__ unsigned smem_u32(const void* p){
    unsigned a; asm("{ .reg .u64 t; cvta.to.shared.u64 t, %1; cvt.u32.u64 %0, t; }":"=r"(a):"l"(p)); return a;
}
static __device__ __forceinline__ unsigned pack_bf16x2(float lo, float hi){
    unsigned r; asm("cvt.rn.bf16x2.f32 %0, %1, %2;" : "=r"(r) : "f"(hi), "f"(lo)); return r;
}
static __device__ __forceinline__ float ex2f(float x){
    float r; asm("ex2.approx.f32 %0, %1;" : "=f"(r) : "f"(x)); return r;
}
static __device__ __forceinline__ void ldsm4(unsigned* r, unsigned addr){
    asm volatile("ldmatrix.sync.aligned.m8n8.x4.shared.b16 {%0,%1,%2,%3}, [%4];"
        : "=r"(r[0]),"=r"(r[1]),"=r"(r[2]),"=r"(r[3]) : "r"(addr));
}
static __device__ __forceinline__ void ldsm4t(unsigned* r, unsigned addr){
    asm volatile("ldmatrix.sync.aligned.m8n8.x4.trans.shared.b16 {%0,%1,%2,%3}, [%4];"
        : "=r"(r[0]),"=r"(r[1]),"=r"(r[2]),"=r"(r[3]) : "r"(addr));
}
static __device__ __forceinline__ void mma16816(float* d, const unsigned* a, unsigned b0, unsigned b1){
    asm volatile("mma.sync.aligned.m16n8k16.row.col.f32.bf16.bf16.f32 "
        "{%0,%1,%2,%3}, {%4,%5,%6,%7}, {%8,%9}, {%0,%1,%2,%3};"
        : "+f"(d[0]),"+f"(d[1]),"+f"(d[2]),"+f"(d[3])
        : "r"(a[0]),"r"(a[1]),"r"(a[2]),"r"(a[3]), "r"(b0),"r"(b1));
}
// split-precision bf16: v = hi + lo, hi = truncate-to-bf16(v)
static __device__ __forceinline__ void split_bf16x2(float v0, float v1, unsigned& hi, unsigned& lo){
    unsigned u0 = __float_as_uint(v0), u1 = __float_as_uint(v1);
    asm("prmt.b32 %0, %1, %2, 0x7632;" : "=r"(hi) : "r"(u0), "r"(u1));
    float l0 = v0 - __uint_as_float(u0 & 0xFFFF0000u);
    float l1 = v1 - __uint_as_float(u1 & 0xFFFF0000u);
    lo = pack_bf16x2(l0, l1);
}
#define CPA(dst, src) asm volatile("cp.async.ca.shared.global [%0], [%1], 16;" :: "r"(dst), "l"(src))
#define CP_COMMIT()   asm volatile("cp.async.commit_group;" ::: "memory")
#define CP_WAIT(n)    asm volatile("cp.async.wait_group %0;" :: "n"(n) : "memory")

// ---------------- K1 (bf16x3 mma): x(512) -> fp(64), fcb(64), BN fold ----------------
__global__ __launch_bounds__(256) void kA(
    const float* __restrict__ x,
    const float* __restrict__ wp1, const float* __restrict__ gp1, const float* __restrict__ bp1,
    const float* __restrict__ mp1, const float* __restrict__ vp1,
    const float* __restrict__ wc1, const float* __restrict__ gc1, const float* __restrict__ bc1,
    const float* __restrict__ mc1, const float* __restrict__ vc1)
{
    extern __shared__ char smraw[];
    float* sWf[2] = {(float*)smraw, (float*)(smraw+18432)};
    float* sXf[2] = {(float*)(smraw+36864), (float*)(smraw+36864+8704)};
    unsigned ub = smem_u32(smraw);
    unsigned uW[2] = {ub, ub+18432};
    unsigned uX[2] = {ub+36864, ub+36864+8704};

    int b = blockIdx.y, p0 = blockIdx.x*64;
    int tid=threadIdx.x, lane=tid&31, w=tid>>5;
    int wm=w>>1, wn=w&1;
    const float* xb = x + (size_t)b*CIN*HW + p0;

    const float* wsrc[4]; unsigned wdst[4];
    const float* xsrc[2]; unsigned xdst[2]; int xk[2];
#pragma unroll
    for (int s=0;s<4;s++){
        int idx = tid + s*256;
        int o = idx>>3, kq = (idx&7)*4;
        wsrc[s] = (o<64 ? wp1 + (size_t)o*CIN : wc1 + (size_t)(o-64)*CIN) + kq;
        wdst[s] = (unsigned)((o*36 + kq)*4);
    }
#pragma unroll
    for (int s=0;s<2;s++){
        int idx = tid + s*256;
        int k = idx>>4, pq = (idx&15)*4;
        xk[s] = k;
        xsrc[s] = xb + pq;
        xdst[s] = (unsigned)((k*68 + pq)*4);
    }
#pragma unroll
    for (int s=0;s<4;s++) CPA(uW[0]+wdst[s], wsrc[s]);
#pragma unroll
    for (int s=0;s<2;s++) CPA(uX[0]+xdst[s], xsrc[s] + (size_t)xk[s]*HW);
    CP_COMMIT();

    float acc[2][4][4];
#pragma unroll
    for (int mt=0;mt<2;mt++)
#pragma unroll
        for (int nt=0;nt<4;nt++){ acc[mt][nt][0]=0.f; acc[mt][nt][1]=0.f; acc[mt][nt][2]=0.f; acc[mt][nt][3]=0.f; }

    int orow = wm*32 + (lane>>2);
    int pxr  = wn*32 + (lane>>2);

    for (int c=0;c<16;c++){
        if (c<15){
            int k0 = (c+1)*32; int nb=(c+1)&1;
#pragma unroll
            for (int s=0;s<4;s++) CPA(uW[nb]+wdst[s], wsrc[s]+k0);
#pragma unroll
            for (int s=0;s<2;s++) CPA(uX[nb]+xdst[s], xsrc[s] + (size_t)(k0+xk[s])*HW);
            CP_COMMIT(); CP_WAIT(1);
        } else { CP_WAIT(0); }
        __syncthreads();
        const float* Wb = sWf[c&1]; const float* Xb = sXf[c&1];
#pragma unroll
        for (int kst=0;kst<2;kst++){
            int kk2 = kst*16 + (lane&3)*2;
            unsigned Ah[2][4], Al[2][4];
#pragma unroll
            for (int mt=0;mt<2;mt++){
                int ro = (orow + mt*16)*36;
                float2 p0 = *(const float2*)&Wb[ro + kk2];
                float2 p1 = *(const float2*)&Wb[ro + 8*36 + kk2];
                float2 p2 = *(const float2*)&Wb[ro + kk2 + 8];
                float2 p3 = *(const float2*)&Wb[ro + 8*36 + kk2 + 8];
                split_bf16x2(p0.x, p0.y, Ah[mt][0], Al[mt][0]);
                split_bf16x2(p1.x, p1.y, Ah[mt][1], Al[mt][1]);
                split_bf16x2(p2.x, p2.y, Ah[mt][2], Al[mt][2]);
                split_bf16x2(p3.x, p3.y, Ah[mt][3], Al[mt][3]);
            }
            unsigned Bh[4][2], Bl[4][2];
#pragma unroll
            for (int nt=0;nt<4;nt++){
                int col = pxr + nt*8;
                split_bf16x2(Xb[(kk2  )*68 + col], Xb[(kk2+1)*68 + col], Bh[nt][0], Bl[nt][0]);
                split_bf16x2(Xb[(kk2+8)*68 + col], Xb[(kk2+9)*68 + col], Bh[nt][1], Bl[nt][1]);
            }
#pragma unroll
            for (int mt=0;mt<2;mt++)
#pragma unroll
                for (int nt=0;nt<4;nt++){
                    mma16816(acc[mt][nt], Al[mt], Bh[nt][0], Bh[nt][1]);
                    mma16816(acc[mt][nt], Ah[mt], Bl[nt][0], Bl[nt][1]);
                    mma16816(acc[mt][nt], Ah[mt], Bh[nt][0], Bh[nt][1]);
                }
        }
        __syncthreads();
    }
#pragma unroll
    for (int mt=0;mt<2;mt++){
#pragma unroll
        for (int sel=0;sel<2;sel++){
            int oc = wm*32 + mt*16 + (lane>>2) + sel*8;
            float inv, bias; float* dst;
            if (oc<64){ inv=gp1[oc]*rsqrtf(vp1[oc]+EPS); bias=bp1[oc]-mp1[oc]*inv;
                        dst=g_fp+(size_t)(b*CI+oc)*HW; }
            else      { int o2=oc-64; inv=gc1[o2]*rsqrtf(vc1[o2]+EPS); bias=bc1[o2]-mc1[o2]*inv;
                        dst=g_fcb+(size_t)(b*CI+o2)*HW; }
#pragma unroll
            for (int nt=0;nt<4;nt++){
                float2 v;
                v.x = acc[mt][nt][sel*2+0]*inv+bias;
                v.y = acc[mt][nt][sel*2+1]*inv+bias;
                *(float2*)&dst[p0 + wn*32 + nt*8 + (lane&3)*2] = v;
            }
        }
    }
}

// ---------------- K2: fp(64) -> Q/K/V pixel-major bf16; also zeroes g_gram ----------------
__global__ __launch_bounds__(256) void kB(
    const float* __restrict__ wb,  const float* __restrict__ bb,
    const float* __restrict__ wc2, const float* __restrict__ bc2,
    const float* __restrict__ wd,  const float* __restrict__ bd)
{
    extern __shared__ float sm[];
    float* sW3 = sm;                                   // [3][64][68]
    float (*sF)[68] = (float(*)[68])(sm + 3*64*68);    // [k][p]
    int p0 = blockIdx.x*64, b = blockIdx.y;
    int tid=threadIdx.x, ty=tid>>4, tx=tid&15;

    if (tid < 64) g_gram[(blockIdx.y*64 + blockIdx.x)*64 + tid] = 0.f;

    const float* Ws[3] = {wb, wc2, wd};
#pragma unroll
    for (int sel=0;sel<3;sel++){
        float fac = (sel==0) ? LOG2E : 1.f;
        float* sW = sW3 + sel*64*68;
#pragma unroll
        for (int s=0;s<4;s++){
            int idx = tid + s*256;
            int j = idx>>4, cc = (idx&15)*4;
            float4 v = *(const float4*)(Ws[sel] + j*64 + cc);
            sW[(cc+0)*68+j]=v.x*fac; sW[(cc+1)*68+j]=v.y*fac; sW[(cc+2)*68+j]=v.z*fac; sW[(cc+3)*68+j]=v.w*fac;
        }
    }
    const float* fpb = g_fp + (size_t)b*CI*HW + p0;
#pragma unroll
    for (int s=0;s<4;s++){
        int idx = tid + s*256;
        int k = idx>>4, pc = (idx&15)*4;
        *(float4*)&sF[k][pc] = *(const float4*)(fpb + (size_t)k*HW + pc);
    }
    __syncthreads();
    const float* biasArr[3] = {bb, bc2, bd};
    __nv_bfloat16* dsts[3] = {g_fbt, g_fct, g_fdt};
#pragma unroll
    for (int sel=0;sel<3;sel++){
        float fac = (sel==0) ? LOG2E : 1.f;
        const float* sW = sW3 + sel*64*68;
        const float* bias = biasArr[sel];
        float acc[4][4];
#pragma unroll
        for (int i=0;i<4;i++)
#pragma unroll
            for (int j=0;j<4;j++) acc[i][j]=0.f;
        for (int k=0;k<64;k++){
            float a[4], bv[4];
#pragma unroll
            for (int i=0;i<4;i++) a[i]=sW[k*68 + ty*4+i];
#pragma unroll
            for (int j=0;j<4;j++) bv[j]=sF[k][tx*4+j];
#pragma unroll
            for (int i=0;i<4;i++)
#pragma unroll
                for (int j=0;j<4;j++)
                    acc[i][j] = fmaf(a[i], bv[j], acc[i][j]);
        }
        __nv_bfloat16* dstT = dsts[sel] + ((size_t)b*HW + p0)*CI;
        float bi0=bias[ty*4+0]*fac, bi1=bias[ty*4+1]*fac, bi2=bias[ty*4+2]*fac, bi3=bias[ty*4+3]*fac;
#pragma unroll
        for (int j=0;j<4;j++){
            uint2 v;
            v.x = pack_bf16x2(acc[0][j]+bi0, acc[1][j]+bi1);
            v.y = pack_bf16x2(acc[2][j]+bi2, acc[3][j]+bi3);
            *(uint2*)((char*)dstT + ((size_t)(tx*4+j)*CI + ty*4)*2) = v;
        }
    }
}

// ---------------- K3: flash attention + fused Gram tail ----------------
// grid (32 q-blocks, 4 k-splits, 4 batch), 256 thr
// each CTA also computes one 32-px Gram chunk (chunk = x + 32*ks) at the end
#define QSTR 144   // bytes per smem row (72 bf16)
__global__ __launch_bounds__(256) void kCm()
{
    extern __shared__ char smem[];
    const int SKb0=0, SKb1=18432, SVb0=36864, SVb1=55296;
    float* sOut = (float*)smem;
    unsigned sb = smem_u32(smem);
    int tid=threadIdx.x, lane=tid&31, w=tid>>5;
    int b=blockIdx.z, ks=blockIdx.y, q0=blockIdx.x*128;
    int g = lane>>2, tg = lane&3;
    const int NT = 32/NSPLIT;
    const int T0 = ks*NT;

    const char* Qg = (const char*)(g_fbt + ((size_t)b*HW + q0)*CI);
    const char* Kg = (const char*)(g_fct + (size_t)b*HW*CI);
    const char* Vg = (const char*)(g_fdt + (size_t)b*HW*CI);

    int pxl[4], chl[4];
#pragma unroll
    for (int s=0;s<4;s++){ int idx = tid + s*256; pxl[s]=idx>>3; chl[s]=(idx&7)*8; }

#pragma unroll
    for (int s=0;s<4;s++){
        unsigned so = (unsigned)(pxl[s]*QSTR + chl[s]*2);
        size_t  go = ((size_t)pxl[s]*CI + chl[s])*2;
        size_t  gk = (((size_t)T0*128 + pxl[s])*CI + chl[s])*2;
        CPA(sb+SKb1+so, Qg + go);
        CPA(sb+SKb0+so, Kg + gk);
        CPA(sb+SVb0+so, Vg + gk);
    }
    CP_COMMIT(); CP_WAIT(0);
    __syncthreads();

    unsigned aQ[4][4];
    {
        unsigned rb = sb + SKb1 + (unsigned)((16*w + (lane&15))*QSTR) + (unsigned)((lane>>4)*16);
#pragma unroll
        for (int kq=0; kq<4; kq++) ldsm4(aQ[kq], rb + kq*32);
    }
    __syncthreads();

    float oacc[8][4];
#pragma unroll
    for (int i=0;i<8;i++){ oacc[i][0]=0.f; oacc[i][1]=0.f; oacc[i][2]=0.f; oacc[i][3]=0.f; }
    float lr0 = 0.f, lr1 = 0.f;

    for (int tt=0; tt<NT; tt++){
        if (tt<NT-1){
            unsigned SKn = ((tt+1)&1)? SKb1 : SKb0;
            unsigned SVn = ((tt+1)&1)? SVb1 : SVb0;
            size_t kn = (size_t)(T0+tt+1)*128;
#pragma unroll
            for (int s=0;s<4;s++){
                unsigned so = (unsigned)(pxl[s]*QSTR + chl[s]*2);
                size_t  go = ((kn + pxl[s])*CI + chl[s])*2;
                CPA(sb+SKn+so, Kg + go);
                CPA(sb+SVn+so, Vg + go);
            }
            CP_COMMIT(); CP_WAIT(1);
        } else { CP_WAIT(0); }
        __syncthreads();

        unsigned SKc = (tt&1)? SKb1 : SKb0;
        unsigned SVc = (tt&1)? SVb1 : SVb0;

        float sacc[16][4];
#pragma unroll
        for (int nt=0; nt<16; nt++){ sacc[nt][0]=0.f; sacc[nt][1]=0.f; sacc[nt][2]=0.f; sacc[nt][3]=0.f; }
#pragma unroll
        for (int nt=0; nt<16; nt++){
            unsigned addr = sb + SKc + (unsigned)((nt*8 + (lane&7))*QSTR) + (unsigned)((lane>>3)*16);
            unsigned b0[4], b1[4];
            ldsm4(b0, addr);
            ldsm4(b1, addr + 64);
            mma16816(sacc[nt], aQ[0], b0[0], b0[1]);
            mma16816(sacc[nt], aQ[1], b0[2], b0[3]);
            mma16816(sacc[nt], aQ[2], b1[0], b1[1]);
            mma16816(sacc[nt], aQ[3], b1[2], b1[3]);
        }

        unsigned aP[8][4];
#pragma unroll
        for (int nt=0; nt<16; nt++){
            float e0 = ex2f(sacc[nt][0]);
            float e1 = ex2f(sacc[nt][1]);
            float e2 = ex2f(sacc[nt][2]);
            float e3 = ex2f(sacc[nt][3]);
            lr0 += e0 + e1; lr1 += e2 + e3;
            sacc[nt][0]=e0; sacc[nt][1]=e1; sacc[nt][2]=e2; sacc[nt][3]=e3;
        }
#pragma unroll
        for (int s2=0; s2<8; s2++){
            aP[s2][0] = pack_bf16x2(sacc[2*s2  ][0], sacc[2*s2  ][1]);
            aP[s2][1] = pack_bf16x2(sacc[2*s2  ][2], sacc[2*s2  ][3]);
            aP[s2][2] = pack_bf16x2(sacc[2*s2+1][0], sacc[2*s2+1][1]);
            aP[s2][3] = pack_bf16x2(sacc[2*s2+1][2], sacc[2*s2+1][3]);
        }

#pragma unroll
        for (int s2=0; s2<8; s2++){
            unsigned rowa = (unsigned)((s2*16 + (lane&7) + ((lane>>3)&1)*8)*QSTR);
#pragma unroll
            for (int cp=0; cp<4; cp++){
                unsigned addr = sb + SVc + rowa + (unsigned)(cp*32 + (lane>>4)*16);
                unsigned bv[4];
                ldsm4t(bv, addr);
                mma16816(oacc[2*cp  ], aP[s2], bv[0], bv[1]);
                mma16816(oacc[2*cp+1], aP[s2], bv[2], bv[3]);
            }
        }
        __syncthreads();
    }

#pragma unroll
    for (int off=1; off<4; off<<=1){
        lr0 += __shfl_xor_sync(0xffffffffu, lr0, off);
        lr1 += __shfl_xor_sync(0xffffffffu, lr1, off);
    }
    int qr0 = 16*w + g, qr1 = qr0 + 8;
    if (tg==0){
        g_lsum[((size_t)ks*BB_ + b)*HW + q0 + qr0] = lr0;
        g_lsum[((size_t)ks*BB_ + b)*HW + q0 + qr1] = lr1;
    }
#pragma unroll
    for (int ct=0; ct<8; ct++){
#pragma unroll
        for (int jj=0; jj<2; jj++){
            int c = ct*8 + 2*tg + jj;
            sOut[c*132 + qr0] = oacc[ct][jj];
            sOut[c*132 + qr1] = oacc[ct][2+jj];
        }
    }
    __syncthreads();
    float* op = g_opart + (size_t)ks*BB_*CI*HW + (size_t)b*CI*HW + q0;
#pragma unroll
    for (int s=0;s<8;s++){
        int idx = tid + s*256; int c = idx>>5, p4 = (idx&31)*4;
        float4 f;
        f.x = sOut[c*132 + p4+0];
        f.y = sOut[c*132 + p4+1];
        f.z = sOut[c*132 + p4+2];
        f.w = sOut[c*132 + p4+3];
        *(float4*)(op + (size_t)c*HW + p4) = f;
    }

    // ---- fused Gram tail: 32-px chunk (chunk = x + 32*ks), atomic reduce ----
    __syncthreads();   // sOut reads complete; reuse smem for fcb stage
    {
        float (*sG32)[68] = (float(*)[68])smem;   // [n 0..31][c 0..63]
        int pg0 = (blockIdx.x + 32*ks)*32;
        const float* fab = g_fcb + (size_t)b*CI*HW + pg0;
#pragma unroll
        for (int s=0;s<2;s++){
            int idx = tid + s*256;                // 512 float4 = 64ch x 8
            int c = idx>>3, nc = (idx&7)*4;
            float4 v = *(const float4*)(fab + (size_t)c*HW + nc);
            sG32[nc+0][c]=v.x; sG32[nc+1][c]=v.y; sG32[nc+2][c]=v.z; sG32[nc+3][c]=v.w;
        }
        __syncthreads();
        int ty=tid>>4, tx=tid&15;
        float gacc[4][4];
#pragma unroll
        for (int i=0;i<4;i++)
#pragma unroll
            for (int j=0;j<4;j++) gacc[i][j]=0.f;
#pragma unroll 4
        for (int n=0;n<32;n++){
            float4 a4 = *(float4*)&sG32[n][ty*4];
            float4 b4 = *(float4*)&sG32[n][tx*4];
            float a[4]={a4.x,a4.y,a4.z,a4.w}, bv[4]={b4.x,b4.y,b4.z,b4.w};
#pragma unroll
            for (int i=0;i<4;i++)
#pragma unroll
                for (int j=0;j<4;j++)
                    gacc[i][j] = fmaf(a[i], bv[j], gacc[i][j]);
        }
        float* G = g_gram + b*CI*CI;
#pragma unroll
        for (int i=0;i<4;i++)
#pragma unroll
            for (int j=0;j<4;j++)
                atomicAdd(&G[(ty*4+i)*CI + tx*4+j], gacc[i][j]);
    }
}

// ---------------- K5 (fused softC+D+E): channel softmax + fusion + out conv ----------------
// 64-px tiles, grid (64 px, 4 batch), 256 thr, double-buffered weights
__global__ __launch_bounds__(256) void kDE(
    const float* __restrict__ beta, const float* __restrict__ alpha,
    const float* __restrict__ wo, const float* __restrict__ go, const float* __restrict__ bo,
    const float* __restrict__ mo, const float* __restrict__ vo, float* __restrict__ out)
{
    extern __shared__ float sm[];
    float (*sAt)[68] = (float(*)[68])sm;                // attn^T [d][c]
    float (*sFu)[68] = (float(*)[68])(sm + 64*68);      // fcb -> fusion tile
    float* sRs = sm + 2*64*68;                          // [64]
    float* sWb[2] = { sm + 2*64*68 + 64, sm + 2*64*68 + 64 + 128*68 };
    float (*sG)[68] = (float(*)[68])sWb[1];             // gram staged in buf1 pre-prefetch
    unsigned uWb[2] = { smem_u32(sWb[0]), smem_u32(sWb[1]) };

    int p0=blockIdx.x*64, b=blockIdx.y;
    int tid=threadIdx.x, lane=tid&31, w=tid>>5;
    int ty=tid>>4, tx=tid&15;
    int wm=w>>1, wn=w&1;

    // issue ob=0 weights into buf0 immediately (group 0)
#pragma unroll
    for (int s=0;s<8;s++){
        int idx = tid + s*256;
        int o = idx>>4, kq = (idx&15)*4;
        CPA(uWb[0] + (unsigned)((o*68 + kq)*4), wo + (size_t)o*CI + kq);
    }
    CP_COMMIT();

    // ---- phase 0: gram (into buf1 space) + fcb + lsum; channel softmax -> sAt ----
#pragma unroll
    for (int s=0;s<4;s++){
        int idx=tid+s*256; int c=idx>>4, dc=(idx&15)*4;
        *(float4*)&sG[c][dc] = *(const float4*)(g_gram + b*CI*CI + c*CI + dc);
    }
    const float* fab = g_fcb + (size_t)b*CI*HW + p0;
#pragma unroll
    for (int s=0;s<4;s++){
        int idx=tid+s*256; int d=idx>>4, pc=(idx&15)*4;
        *(float4*)&sFu[d][pc] = *(const float4*)(fab + (size_t)d*HW + pc);
    }
    if (tid < 64){
        float l = 0.f;
#pragma unroll
        for (int ksl=0; ksl<NSPLIT; ksl++)
            l += g_lsum[((size_t)ksl*BB_ + b)*HW + p0 + tid];
        sRs[tid] = __ldg(alpha) / l;
    }
    __syncthreads();
    {
        int rc = tid>>2, rq = tid&3;
        float e[16];
        float vmin = 1e30f;
#pragma unroll
        for (int j=0;j<16;j++) vmin = fminf(vmin, sG[rc][rq*16+j]);
        vmin = fminf(vmin, __shfl_xor_sync(0xffffffffu, vmin, 1));
        vmin = fminf(vmin, __shfl_xor_sync(0xffffffffu, vmin, 2));
        float sum = 0.f;
#pragma unroll
        for (int j=0;j<16;j++){ e[j] = expf(vmin - sG[rc][rq*16+j]); sum += e[j]; }
        sum += __shfl_xor_sync(0xffffffffu, sum, 1);
        sum += __shfl_xor_sync(0xffffffffu, sum, 2);
        float rs = 1.f/sum;
#pragma unroll
        for (int j=0;j<16;j++) sAt[rq*16+j][rc] = e[j]*rs;
    }
    __syncthreads();   // gram fully consumed; buf1 free for ob=1 weights

    // issue ob=1 weights into buf1 (group 1)
#pragma unroll
    for (int s=0;s<8;s++){
        int idx = tid + s*256;
        int o = idx>>4, kq = (idx&15)*4;
        CPA(uWb[1] + (unsigned)((o*68 + kq)*4), wo + (size_t)(128+o)*CI + kq);
    }
    CP_COMMIT();

    // ---- phase 1: acc1 = attn @ fcb; fusion into sFu ----
    float acc1[4][4];
#pragma unroll
    for (int i=0;i<4;i++)
#pragma unroll
        for (int j=0;j<4;j++) acc1[i][j]=0.f;
#pragma unroll 4
    for (int d=0;d<64;d++){
        float4 a4 = *(float4*)&sAt[d][ty*4];
        float a[4]={a4.x,a4.y,a4.z,a4.w};
        float4 b4 = *(float4*)&sFu[d][tx*4];
        float bv[4]={b4.x,b4.y,b4.z,b4.w};
#pragma unroll
        for (int i=0;i<4;i++)
#pragma unroll
            for (int j=0;j<4;j++)
                acc1[i][j] = fmaf(a[i], bv[j], acc1[i][j]);
    }
    __syncthreads();
    float bt = __ldg(beta);
    const size_t OSZ = (size_t)BB_*CI*HW;
#pragma unroll
    for (int i=0;i<4;i++){
        int c = ty*4+i;
        int pxb = tx*4;
        size_t off = (size_t)(b*CI+c)*HW + p0 + pxb;
        float4 fp4  = *(const float4*)(g_fp    + off);
        float4 osum = *(const float4*)(g_opart + off);
#pragma unroll
        for (int ksl=1; ksl<NSPLIT; ksl++){
            float4 oo = *(const float4*)(g_opart + (size_t)ksl*OSZ + off);
            osum.x += oo.x; osum.y += oo.y; osum.z += oo.z; osum.w += oo.w;
        }
        float fcx = sFu[c][pxb+0], fcy = sFu[c][pxb+1], fcz = sFu[c][pxb+2], fcw = sFu[c][pxb+3];
        sFu[c][pxb+0] = fp4.x + sRs[pxb+0]*osum.x + bt*acc1[i][0] + fcx;
        sFu[c][pxb+1] = fp4.y + sRs[pxb+1]*osum.y + bt*acc1[i][1] + fcy;
        sFu[c][pxb+2] = fp4.z + sRs[pxb+2]*osum.z + bt*acc1[i][2] + fcz;
        sFu[c][pxb+3] = fp4.w + sRs[pxb+3]*osum.w + bt*acc1[i][3] + fcw;
    }

    // ---- phase 2 (bf16x3 mma): out conv, 4 o-blocks, double-buffered weights ----
    int orow = wm*32 + (lane>>2);
    int pxr  = wn*32 + (lane>>2);
    for (int ob=0; ob<4; ob++){
        if (ob<3){ CP_WAIT(1); } else { CP_WAIT(0); }
        __syncthreads();
        const float* sW = sWb[ob&1];

        float acc[2][4][4];
#pragma unroll
        for (int mt=0;mt<2;mt++)
#pragma unroll
            for (int nt=0;nt<4;nt++){ acc[mt][nt][0]=0.f; acc[mt][nt][1]=0.f; acc[mt][nt][2]=0.f; acc[mt][nt][3]=0.f; }

#pragma unroll
        for (int kst=0;kst<4;kst++){
            int kk2 = kst*16 + (lane&3)*2;
            unsigned Ah[2][4], Al[2][4];
#pragma unroll
            for (int mt=0;mt<2;mt++){
                int ro = (orow + mt*16)*68;
                float2 p0v = *(const float2*)&sW[ro + kk2];
                float2 p1v = *(const float2*)&sW[ro + 8*68 + kk2];
                float2 p2v = *(const float2*)&sW[ro + kk2 + 8];
                float2 p3v = *(const float2*)&sW[ro + 8*68 + kk2 + 8];
                split_bf16x2(p0v.x, p0v.y, Ah[mt][0], Al[mt][0]);
                split_bf16x2(p1v.x, p1v.y, Ah[mt][1], Al[mt][1]);
                split_bf16x2(p2v.x, p2v.y, Ah[mt][2], Al[mt][2]);
                split_bf16x2(p3v.x, p3v.y, Ah[mt][3], Al[mt][3]);
            }
            unsigned Bh[4][2], Bl[4][2];
#pragma unroll
            for (int nt=0;nt<4;nt++){
                int col = pxr + nt*8;
                split_bf16x2(sFu[kk2  ][col], sFu[kk2+1][col], Bh[nt][0], Bl[nt][0]);
                split_bf16x2(sFu[kk2+8][col], sFu[kk2+9][col], Bh[nt][1], Bl[nt][1]);
            }
#pragma unroll
            for (int mt=0;mt<2;mt++)
#pragma unroll
                for (int nt=0;nt<4;nt++){
                    mma16816(acc[mt][nt], Al[mt], Bh[nt][0], Bh[nt][1]);
                    mma16816(acc[mt][nt], Ah[mt], Bl[nt][0], Bl[nt][1]);
                    mma16816(acc[mt][nt], Ah[mt], Bh[nt][0], Bh[nt][1]);
                }
        }
        __syncthreads();
        if (ob+2 <= 3){
#pragma unroll
            for (int s=0;s<8;s++){
                int idx = tid + s*256;
                int o = idx>>4, kq = (idx&15)*4;
                CPA(uWb[ob&1] + (unsigned)((o*68 + kq)*4), wo + (size_t)((ob+2)*128+o)*CI + kq);
            }
            CP_COMMIT();
        }
#pragma unroll
        for (int mt=0;mt<2;mt++){
#pragma unroll
            for (int sel=0;sel<2;sel++){
                int oc = ob*128 + wm*32 + mt*16 + (lane>>2) + sel*8;
                float inv = go[oc]*rsqrtf(vo[oc]+EPS);
                float bias = bo[oc]-mo[oc]*inv;
                float* dst = out + (size_t)(b*CIN+oc)*HW;
#pragma unroll
                for (int nt=0;nt<4;nt++){
                    float2 v;
                    v.x = acc[mt][nt][sel*2+0]*inv+bias;
                    v.y = acc[mt][nt][sel*2+1]*inv+bias;
                    *(float2*)&dst[p0 + wn*32 + nt*8 + (lane&3)*2] = v;
                }
            }
        }
    }
}

// ---------------- launch ----------------
extern "C" void kernel_launch(void* const* d_in, const int* in_sizes, int n_in,
                              void* d_out, int out_size)
{
    const float* x    = (const float*)d_in[0];
    const float* wp1  = (const float*)d_in[1];
    const float* gp1  = (const float*)d_in[2];
    const float* bp1  = (const float*)d_in[3];
    const float* mp1  = (const float*)d_in[4];
    const float* vp1  = (const float*)d_in[5];
    const float* wc1  = (const float*)d_in[6];
    const float* gc1  = (const float*)d_in[7];
    const float* bc1  = (const float*)d_in[8];
    const float* mc1  = (const float*)d_in[9];
    const float* vc1  = (const float*)d_in[10];
    const float* wb   = (const float*)d_in[11];
    const float* bb   = (const float*)d_in[12];
    const float* wc2  = (const float*)d_in[13];
    const float* bc2  = (const float*)d_in[14];
    const float* wd   = (const float*)d_in[15];
    const float* bd   = (const float*)d_in[16];
    const float* alpha= (const float*)d_in[17];
    const float* beta = (const float*)d_in[18];
    const float* wo   = (const float*)d_in[19];
    const float* go   = (const float*)d_in[20];
    const float* bo   = (const float*)d_in[21];
    const float* mo   = (const float*)d_in[22];
    const float* vo   = (const float*)d_in[23];
    float* out = (float*)d_out;

    const int SMEM_A  = 36864 + 2*8704;                      // 54272
    const int SMEM_B  = (3*64*68 + 64*68) * 4;               // 69632
    const int SMEM_C  = 73728;
    const int SMEM_DE = (2*64*68 + 64 + 2*128*68) * 4;       // 104704
    cudaFuncSetAttribute(kA,  cudaFuncAttributeMaxDynamicSharedMemorySize, SMEM_A);
    cudaFuncSetAttribute(kB,  cudaFuncAttributeMaxDynamicSharedMemorySize, SMEM_B);
    cudaFuncSetAttribute(kCm, cudaFuncAttributeMaxDynamicSharedMemorySize, SMEM_C);
    cudaFuncSetAttribute(kDE, cudaFuncAttributeMaxDynamicSharedMemorySize, SMEM_DE);

    kA<<<dim3(64,4),256,SMEM_A>>>(x, wp1,gp1,bp1,mp1,vp1, wc1,gc1,bc1,mc1,vc1);
    kB<<<dim3(64,4),256,SMEM_B>>>(wb,bb,wc2,bc2,wd,bd);
    kCm<<<dim3(32,NSPLIT,4),256,SMEM_C>>>();
    kDE<<<dim3(64,4),256,SMEM_DE>>>(beta, alpha, wo,go,bo,mo,vo,out);
}